// round 4
// baseline (speedup 1.0000x reference)
#include <cuda_runtime.h>

#define B_ 4
#define T_ 128
#define N_ 512
#define D_ 32
#define JN_ 16384       // (B*T)*D
#define EMB_ 10

typedef unsigned long long u64;

// ---------------- f32x2 packed helpers (sm_103a FFMA2) -----------------------
__device__ __forceinline__ u64 pack2(float lo, float hi) {
    u64 r; asm("mov.b64 %0, {%1, %2};" : "=l"(r) : "f"(lo), "f"(hi)); return r;
}
__device__ __forceinline__ void unpack2(u64 v, float& lo, float& hi) {
    asm("mov.b64 {%0, %1}, %2;" : "=f"(lo), "=f"(hi) : "l"(v));
}
__device__ __forceinline__ u64 fma2(u64 a, u64 b, u64 c) {
    u64 d; asm("fma.rn.f32x2 %0, %1, %2, %3;" : "=l"(d) : "l"(a), "l"(b), "l"(c)); return d;
}
__device__ __forceinline__ u64 mul2(u64 a, u64 b) {
    u64 d; asm("mul.rn.f32x2 %0, %1, %2;" : "=l"(d) : "l"(a), "l"(b)); return d;
}
__device__ __forceinline__ u64 add2(u64 a, u64 b) {
    u64 d; asm("add.rn.f32x2 %0, %1, %2;" : "=l"(d) : "l"(a), "l"(b)); return d;
}
__device__ __forceinline__ u64 relu2(u64 v) {
    float a, b; unpack2(v, a, b);
    return pack2(fmaxf(a, 0.f), fmaxf(b, 0.f));
}

// ---------------- scratch (device globals; no allocations allowed) ----------
__device__ float g_buf0[N_ * JN_];       // layout (n, bt, c), bt = b*T+t
__device__ float g_buf1[N_ * JN_];
__device__ float g_xg[2 * N_ * JN_];     // aggregated supports k=1,2
__device__ float g_S2[N_ * N_];
__device__ float g_W[3 * N_ * 3 * D_ * D_];   // per-layer per-node (k,c,o)
__device__ float g_bias[3 * N_ * D_];

// ---------------- transpose x (bt,n,c) -> (n,bt,c) --------------------------
__global__ void k_transpose(const float* __restrict__ x) {
    int n = blockIdx.x, bt0 = blockIdx.y * 64, tid = threadIdx.x;
#pragma unroll
    for (int j = 0; j < 8; j++) {
        int idx = j * 256 + tid;
        int r = idx >> 5, c = idx & 31;
        g_buf0[n * JN_ + (bt0 + r) * D_ + c] =
            x[(bt0 + r) * (N_ * D_) + n * D_ + c];
    }
}

// ---------------- S2 = 2*adj@adj - I ----------------------------------------
__global__ void k_s2(const float* __restrict__ A) {
    __shared__ float As[32][33], Bs[32][33];
    int by = blockIdx.y, bx = blockIdx.x, tid = threadIdx.x;
    int ty = tid >> 5, tx = tid & 31;
    float acc[4] = {0.f, 0.f, 0.f, 0.f};
    for (int m0 = 0; m0 < N_; m0 += 32) {
#pragma unroll
        for (int i = 0; i < 4; i++) {
            int r = ty + i * 8;
            As[r][tx] = A[(by * 32 + r) * N_ + m0 + tx];
            Bs[r][tx] = A[(m0 + r) * N_ + bx * 32 + tx];
        }
        __syncthreads();
#pragma unroll
        for (int m = 0; m < 32; m++) {
            float b = Bs[m][tx];
#pragma unroll
            for (int i = 0; i < 4; i++) acc[i] += As[ty + i * 8][m] * b;
        }
        __syncthreads();
    }
#pragma unroll
    for (int i = 0; i < 4; i++) {
        int r = by * 32 + ty + i * 8, c = bx * 32 + tx;
        g_S2[r * N_ + c] = 2.f * acc[i] - (r == c ? 1.f : 0.f);
    }
}

// ---------------- per-node GCN weights: W[n,k,c,o] = sum_e E[n,e] gw[e,k,c,o]
__global__ void k_wn(const float* __restrict__ E, const float* __restrict__ gw,
                     const float* __restrict__ gb) {
    int n = blockIdx.x, L = blockIdx.y, tid = threadIdx.x;
    float Er[EMB_];
#pragma unroll
    for (int e = 0; e < EMB_; e++) Er[e] = E[n * EMB_ + e];
    const float* g0 = gw + L * (EMB_ * 3072);
    float* wout = g_W + (L * N_ + n) * 3072;
    for (int idx = tid; idx < 3072; idx += 256) {
        float a = 0.f;
#pragma unroll
        for (int e = 0; e < EMB_; e++) a += Er[e] * g0[e * 3072 + idx];
        wout[idx] = a;
    }
    if (tid < 32) {
        const float* b0 = gb + L * (EMB_ * 32);
        float a = 0.f;
#pragma unroll
        for (int e = 0; e < EMB_; e++) a += Er[e] * b0[e * 32 + tid];
        g_bias[(L * N_ + n) * 32 + tid] = a;
    }
}

// ---------------- aggregation GEMM: [adj;S2](1024x512) @ H(512x16384) -------
// FFMA2 version: A duplicated-packed in smem, acc packed over B-column pairs.
__global__ void __launch_bounds__(256) k_agg(const float* __restrict__ adj,
                                             int inSel) {
    __shared__ u64 As2[16][136];     // dup pairs (a,a); row = 1088B (16B-mult)
    __shared__ float Bs[16][132];
    const float* Hin = inSel ? g_buf1 : g_buf0;
    int bx = blockIdx.x, by = blockIdx.y, tid = threadIdx.x;
    const float* Ap = (by < 4) ? (adj + by * 128 * N_) : (g_S2 + (by - 4) * 128 * N_);
    int bn0 = bx * 128;
    int ty = tid >> 4, tx = tid & 15;
    u64 acc[8][4];
#pragma unroll
    for (int i = 0; i < 8; i++)
#pragma unroll
        for (int j = 0; j < 4; j++) acc[i][j] = 0ULL;

    for (int m0 = 0; m0 < N_; m0 += 16) {
#pragma unroll
        for (int s = 0; s < 2; s++) {
            int q = tid + s * 256;
            int r = q >> 2, c4 = (q & 3) * 4;
            float4 v = *(const float4*)&Ap[r * N_ + m0 + c4];
            As2[c4 + 0][r] = pack2(v.x, v.x);
            As2[c4 + 1][r] = pack2(v.y, v.y);
            As2[c4 + 2][r] = pack2(v.z, v.z);
            As2[c4 + 3][r] = pack2(v.w, v.w);
            int kk = q >> 5, b4 = (q & 31) * 4;
            *(float4*)&Bs[kk][b4] =
                *(const float4*)&Hin[(m0 + kk) * JN_ + bn0 + b4];
        }
        __syncthreads();
#pragma unroll
        for (int kk = 0; kk < 16; kk++) {
            u64 ra[8], rb[4];
            *(ulonglong2*)&ra[0] = *(const ulonglong2*)&As2[kk][ty * 8 + 0];
            *(ulonglong2*)&ra[2] = *(const ulonglong2*)&As2[kk][ty * 8 + 2];
            *(ulonglong2*)&ra[4] = *(const ulonglong2*)&As2[kk][ty * 8 + 4];
            *(ulonglong2*)&ra[6] = *(const ulonglong2*)&As2[kk][ty * 8 + 6];
            *(ulonglong2*)&rb[0] = *(const ulonglong2*)&Bs[kk][tx * 8 + 0];
            *(ulonglong2*)&rb[2] = *(const ulonglong2*)&Bs[kk][tx * 8 + 4];
#pragma unroll
            for (int i = 0; i < 8; i++)
#pragma unroll
                for (int j = 0; j < 4; j++)
                    acc[i][j] = fma2(ra[i], rb[j], acc[i][j]);
        }
        __syncthreads();
    }
    int r0 = by * 128 + ty * 8;
#pragma unroll
    for (int i = 0; i < 8; i++) {
        float* o = &g_xg[(r0 + i) * JN_ + bn0 + tx * 8];
        *(ulonglong2*)&o[0] = make_ulonglong2(acc[i][0], acc[i][1]);
        *(ulonglong2*)&o[4] = make_ulonglong2(acc[i][2], acc[i][3]);
    }
}

// ---------------- combine (FFMA2): out = [H|xg1|xg2] @ W[n] + b[n] ----------
// dynamic smem: Ws2 dup u64[3072] (24576B) + Xin float[96][68] (26112B)
#define CMB_SMEM (24576 + 26112)
__global__ void __launch_bounds__(128) k_combine(int inSel, int L) {
    extern __shared__ char csm[];
    u64* Ws2 = (u64*)csm;
    float (*Xin)[68] = (float(*)[68])(csm + 24576);
    __shared__ float bs[32];
    const float* Hin = inSel ? g_buf1 : g_buf0;
    float* Hout = inSel ? g_buf0 : g_buf1;
    int n = blockIdx.x, bt0 = blockIdx.y * 64, tid = threadIdx.x;
    const float* Wl = g_W + (L * N_ + n) * 3072;
    for (int q = tid; q < 3072; q += 128) {
        float v = Wl[q];
        Ws2[q] = pack2(v, v);
    }
    if (tid < 32) bs[tid] = g_bias[(L * N_ + n) * 32 + tid];
    const float* s0 = Hin + n * JN_ + bt0 * D_;
    const float* s1 = g_xg + n * JN_ + bt0 * D_;
    const float* s2 = g_xg + (N_ + n) * JN_ + bt0 * D_;
#pragma unroll
    for (int q = tid; q < 2048; q += 128) {
        int r = q >> 5, c = q & 31;
        Xin[c][r] = s0[q];
        Xin[32 + c][r] = s1[q];
        Xin[64 + c][r] = s2[q];
    }
    __syncthreads();
    int to = tid & 7, tb = tid >> 3;  // cols to*4..+3, bts tb*4..+3
    u64 acc[2][4];
#pragma unroll
    for (int p = 0; p < 2; p++)
#pragma unroll
        for (int j = 0; j < 4; j++) acc[p][j] = 0ULL;
    for (int kc = 0; kc < 96; kc++) {
        u64 xp[2], wd[4];
        *(ulonglong2*)&xp[0] = *(const ulonglong2*)&Xin[kc][tb * 4];   // bt pairs
        *(ulonglong2*)&wd[0] = *(const ulonglong2*)&Ws2[kc * 32 + to * 4 + 0];
        *(ulonglong2*)&wd[2] = *(const ulonglong2*)&Ws2[kc * 32 + to * 4 + 2];
#pragma unroll
        for (int p = 0; p < 2; p++)
#pragma unroll
            for (int j = 0; j < 4; j++)
                acc[p][j] = fma2(xp[p], wd[j], acc[p][j]);
    }
    float4 bv = *(const float4*)&bs[to * 4];
#pragma unroll
    for (int p = 0; p < 2; p++) {
        float lo[4], hi[4];
#pragma unroll
        for (int j = 0; j < 4; j++) unpack2(acc[p][j], lo[j], hi[j]);
        int bt = bt0 + tb * 4 + 2 * p;
        *(float4*)&Hout[n * JN_ + bt * D_ + to * 4] =
            make_float4(lo[0] + bv.x, lo[1] + bv.y, lo[2] + bv.z, lo[3] + bv.w);
        *(float4*)&Hout[n * JN_ + (bt + 1) * D_ + to * 4] =
            make_float4(hi[0] + bv.x, hi[1] + bv.y, hi[2] + bv.z, hi[3] + bv.w);
    }
}

// ---------------- fused TCN: f32x2-packed, 2 sequences per block ------------
// dynamic smem: e01(16KB) wd2(8KB) bb(256B) y0(33KB) y1(33KB) = 90880 B
#define TCN_SMEM 90880
__global__ void __launch_bounds__(128)
k_tcn(const float* __restrict__ w1, const float* __restrict__ b1,
      const float* __restrict__ w2, const float* __restrict__ b2, int sel) {
    extern __shared__ char dsm[];
    ulonglong2* e01 = (ulonglong2*)dsm;                 // [1024] {dup w0, dup w1}
    u64* wd2 = (u64*)(dsm + 16384);                     // [1024] dup w2
    u64* bb  = (u64*)(dsm + 16384 + 8192);              // [32] dup bias
    u64 (*y0)[129] = (u64(*)[129])(dsm + 24832);        // [32][129] packed pair
    u64 (*y1)[129] = (u64(*)[129])(dsm + 24832 + 33024);

    float* base = sel ? g_buf1 : g_buf0;
    float* seqA = base + (2 * blockIdx.x) * 4096;
    float* seqB = seqA + 4096;
    int t = threadIdx.x;

#pragma unroll
    for (int j = 0; j < 32; j++) {
        int idx = j * 128 + t;
        int c = idx & 31, tt = idx >> 5;
        y0[c][tt] = pack2(seqA[idx], seqB[idx]);
    }
    for (int blk = 0; blk < 3; blk++) {
        int dil = 1 << blk;
        __syncthreads();   // y0 ready; previous weight readers done
        const float* ws = w1 + blk * 3072;
        for (int q = t; q < 1024; q += 128) {
            float a = ws[q * 3], b = ws[q * 3 + 1], c = ws[q * 3 + 2];
            e01[q] = make_ulonglong2(pack2(a, a), pack2(b, b));
            wd2[q] = pack2(c, c);
        }
        if (t < 32) { float v = b1[blk * 32 + t]; bb[t] = pack2(v, v); }
        __syncthreads();
        u64 acc[32];
#pragma unroll
        for (int o = 0; o < 32; o++) acc[o] = bb[o];
        for (int c = 0; c < 32; c++) {
            u64 i0 = (t >= 2 * dil) ? y0[c][t - 2 * dil] : 0ULL;
            u64 i1 = (t >= dil) ? y0[c][t - dil] : 0ULL;
            u64 i2 = y0[c][t];
#pragma unroll
            for (int o = 0; o < 32; o++) {
                ulonglong2 w01 = e01[o * 32 + c];
                acc[o] = fma2(w01.x, i0, acc[o]);
                acc[o] = fma2(w01.y, i1, acc[o]);
                acc[o] = fma2(wd2[o * 32 + c], i2, acc[o]);
            }
        }
#pragma unroll
        for (int o = 0; o < 32; o++) y1[o][t] = relu2(acc[o]);
        __syncthreads();   // y1 visible; conv1 weights dead
        const float* ws2 = w2 + blk * 3072;
        for (int q = t; q < 1024; q += 128) {
            float a = ws2[q * 3], b = ws2[q * 3 + 1], c = ws2[q * 3 + 2];
            e01[q] = make_ulonglong2(pack2(a, a), pack2(b, b));
            wd2[q] = pack2(c, c);
        }
        if (t < 32) { float v = b2[blk * 32 + t]; bb[t] = pack2(v, v); }
        __syncthreads();
#pragma unroll
        for (int o = 0; o < 32; o++) acc[o] = bb[o];
        for (int c = 0; c < 32; c++) {
            u64 i0 = (t >= 2 * dil) ? y1[c][t - 2 * dil] : 0ULL;
            u64 i1 = (t >= dil) ? y1[c][t - dil] : 0ULL;
            u64 i2 = y1[c][t];
#pragma unroll
            for (int o = 0; o < 32; o++) {
                ulonglong2 w01 = e01[o * 32 + c];
                acc[o] = fma2(w01.x, i0, acc[o]);
                acc[o] = fma2(w01.y, i1, acc[o]);
                acc[o] = fma2(wd2[o * 32 + c], i2, acc[o]);
            }
        }
        // residual + relu; thread touches only its own column t of y0
#pragma unroll
        for (int o = 0; o < 32; o++)
            y0[o][t] = relu2(add2(relu2(acc[o]), y0[o][t]));
    }
    __syncthreads();
#pragma unroll
    for (int j = 0; j < 32; j++) {
        int idx = j * 128 + t;
        int c = idx & 31, tt = idx >> 5;
        float lo, hi; unpack2(y0[c][tt], lo, hi);
        seqA[idx] = lo; seqB[idx] = hi;
    }
}

// ---------------- temporal attention + layernorm, f32x2 head-packed ---------
__global__ void __launch_bounds__(128)
k_attn(const float* __restrict__ wq, const float* __restrict__ wk,
       const float* __restrict__ wv, const float* __restrict__ wo,
       const float* __restrict__ gga, const float* __restrict__ bba,
       int sel, float* __restrict__ finalOut) {
    __shared__ ulonglong2 Kp[128][8];   // (K[t][d], K[t][d+16]) pairs
    __shared__ ulonglong2 Vp[128][8];
    __shared__ ulonglong2 Wq2[32][8];   // (W[c][d], W[c][d+16]); reused for Wo
    __shared__ ulonglong2 Wk2[32][8];
    __shared__ ulonglong2 Wv2[32][8];
    __shared__ float gs[32], bs2[32];
    float* seq = (sel ? g_buf1 : g_buf0) + blockIdx.x * 4096;
    int t = threadIdx.x;

    u64* Wq2u = (u64*)Wq2; u64* Wk2u = (u64*)Wk2; u64* Wv2u = (u64*)Wv2;
    for (int idx = t; idx < 512; idx += 128) {
        int c = idx >> 4, d = idx & 15;
        Wq2u[c * 16 + d] = pack2(wq[c * 32 + d], wq[c * 32 + d + 16]);
        Wk2u[c * 16 + d] = pack2(wk[c * 32 + d], wk[c * 32 + d + 16]);
        Wv2u[c * 16 + d] = pack2(wv[c * 32 + d], wv[c * 32 + d + 16]);
    }
    if (t < 32) { gs[t] = gga[t]; bs2[t] = bba[t]; }
    __syncthreads();

    float hrow[32];
#pragma unroll
    for (int o4 = 0; o4 < 8; o4++)
        *(float4*)&hrow[o4 * 4] = *(const float4*)&seq[t * 32 + o4 * 4];

    u64 qp[16], tv[16];
#pragma unroll
    for (int d = 0; d < 16; d++) qp[d] = 0ULL;
    for (int c = 0; c < 32; c++) {
        u64 hd = pack2(hrow[c], hrow[c]);
#pragma unroll
        for (int j = 0; j < 8; j++) {
            ulonglong2 w = Wq2[c][j];
            qp[2 * j] = fma2(w.x, hd, qp[2 * j]);
            qp[2 * j + 1] = fma2(w.y, hd, qp[2 * j + 1]);
        }
    }
    u64 qsc = pack2(0.25f, 0.25f);   // 1/sqrt(16)
#pragma unroll
    for (int d = 0; d < 16; d++) qp[d] = mul2(qp[d], qsc);

#pragma unroll
    for (int d = 0; d < 16; d++) tv[d] = 0ULL;
    for (int c = 0; c < 32; c++) {
        u64 hd = pack2(hrow[c], hrow[c]);
#pragma unroll
        for (int j = 0; j < 8; j++) {
            ulonglong2 w = Wk2[c][j];
            tv[2 * j] = fma2(w.x, hd, tv[2 * j]);
            tv[2 * j + 1] = fma2(w.y, hd, tv[2 * j + 1]);
        }
    }
#pragma unroll
    for (int j = 0; j < 8; j++) Kp[t][j] = make_ulonglong2(tv[2 * j], tv[2 * j + 1]);

#pragma unroll
    for (int d = 0; d < 16; d++) tv[d] = 0ULL;
    for (int c = 0; c < 32; c++) {
        u64 hd = pack2(hrow[c], hrow[c]);
#pragma unroll
        for (int j = 0; j < 8; j++) {
            ulonglong2 w = Wv2[c][j];
            tv[2 * j] = fma2(w.x, hd, tv[2 * j]);
            tv[2 * j + 1] = fma2(w.y, hd, tv[2 * j + 1]);
        }
    }
#pragma unroll
    for (int j = 0; j < 8; j++) Vp[t][j] = make_ulonglong2(tv[2 * j], tv[2 * j + 1]);
    __syncthreads();                    // Kp/Vp ready; Wq dead from here
    for (int idx = t; idx < 512; idx += 128) {
        int c = idx >> 4, d = idx & 15;
        Wq2u[c * 16 + d] = pack2(wo[c * 32 + d], wo[c * 32 + d + 16]);  // overlay Wo
    }

    float m0 = -3e38f, l0 = 0.f, m1 = -3e38f, l1 = 0.f;
    u64 acc[16];
#pragma unroll
    for (int d = 0; d < 16; d++) acc[d] = 0ULL;
    for (int kp = 0; kp < 128; kp++) {
        u64 s = 0ULL;
#pragma unroll
        for (int j = 0; j < 8; j++) {
            ulonglong2 k2 = Kp[kp][j];
            s = fma2(qp[2 * j], k2.x, s);
            s = fma2(qp[2 * j + 1], k2.y, s);
        }
        float s0, s1; unpack2(s, s0, s1);
        float nm0 = fmaxf(m0, s0), nm1 = fmaxf(m1, s1);
        float cf0 = __expf(m0 - nm0), cf1 = __expf(m1 - nm1);
        float p0 = __expf(s0 - nm0), p1 = __expf(s1 - nm1);
        l0 = l0 * cf0 + p0; l1 = l1 * cf1 + p1;
        m0 = nm0; m1 = nm1;
        u64 cfp = pack2(cf0, cf1), pp = pack2(p0, p1);
#pragma unroll
        for (int j = 0; j < 8; j++) {
            ulonglong2 v2 = Vp[kp][j];
            acc[2 * j] = fma2(acc[2 * j], cfp, mul2(pp, v2.x));
            acc[2 * j + 1] = fma2(acc[2 * j + 1], cfp, mul2(pp, v2.y));
        }
    }
    u64 inv = pack2(1.f / l0, 1.f / l1);
    float ov[32];
#pragma unroll
    for (int d = 0; d < 16; d++) {
        u64 a = mul2(acc[d], inv);
        unpack2(a, ov[d], ov[d + 16]);
    }
    __syncthreads();                    // Wo overlay fully visible

    u64 rp[16];
#pragma unroll
    for (int d = 0; d < 16; d++)
        rp[d] = pack2(seq[t * 32 + d], seq[t * 32 + d + 16]);   // residual
    for (int c = 0; c < 32; c++) {
        u64 od = pack2(ov[c], ov[c]);
#pragma unroll
        for (int j = 0; j < 8; j++) {
            ulonglong2 w = Wq2[c][j];    // Wo
            rp[2 * j] = fma2(w.x, od, rp[2 * j]);
            rp[2 * j + 1] = fma2(w.y, od, rp[2 * j + 1]);
        }
    }
    float r[32];
#pragma unroll
    for (int d = 0; d < 16; d++) unpack2(rp[d], r[d], r[d + 16]);
    float mu = 0.f;
#pragma unroll
    for (int o = 0; o < 32; o++) mu += r[o];
    mu *= (1.f / 32.f);
    float var = 0.f;
#pragma unroll
    for (int o = 0; o < 32; o++) { float d = r[o] - mu; var += d * d; }
    var *= (1.f / 32.f);
    float rs = rsqrtf(var + 1e-5f);
#pragma unroll
    for (int o = 0; o < 32; o++) r[o] = (r[o] - mu) * rs * gs[o] + bs2[o];

    if (finalOut == nullptr) {
#pragma unroll
        for (int o4 = 0; o4 < 8; o4++)
            *(float4*)&seq[t * 32 + o4 * 4] =
                make_float4(r[o4 * 4], r[o4 * 4 + 1], r[o4 * 4 + 2], r[o4 * 4 + 3]);
    } else {
        int n = blockIdx.x >> 2, b = blockIdx.x & 3;   // seq chunk = n*B + b
        float* dst = finalOut + ((b * T_ + t) * N_ + n) * D_;
#pragma unroll
        for (int o4 = 0; o4 < 8; o4++)
            *(float4*)&dst[o4 * 4] =
                make_float4(r[o4 * 4], r[o4 * 4 + 1], r[o4 * 4 + 2], r[o4 * 4 + 3]);
    }
}

// ---------------- launcher ---------------------------------------------------
extern "C" void kernel_launch(void* const* d_in, const int* in_sizes, int n_in,
                              void* d_out, int out_size) {
    (void)in_sizes; (void)n_in; (void)out_size;
    const float* x   = (const float*)d_in[0];
    const float* E   = (const float*)d_in[2];
    const float* adj = (const float*)d_in[3];
    const float* gw  = (const float*)d_in[4];
    const float* gb  = (const float*)d_in[5];
    const float* tw1 = (const float*)d_in[6];
    const float* tb1 = (const float*)d_in[7];
    const float* tw2 = (const float*)d_in[8];
    const float* tb2 = (const float*)d_in[9];
    const float* awq = (const float*)d_in[10];
    const float* awk = (const float*)d_in[11];
    const float* awv = (const float*)d_in[12];
    const float* awo = (const float*)d_in[13];
    const float* ag  = (const float*)d_in[14];
    const float* ab  = (const float*)d_in[15];
    float* out = (float*)d_out;

    cudaFuncSetAttribute(k_tcn, cudaFuncAttributeMaxDynamicSharedMemorySize,
                         TCN_SMEM);
    cudaFuncSetAttribute(k_combine, cudaFuncAttributeMaxDynamicSharedMemorySize,
                         CMB_SMEM);

    k_transpose<<<dim3(N_, 8), 256>>>(x);
    k_s2<<<dim3(16, 16), 256>>>(adj);
    k_wn<<<dim3(N_, 3), 256>>>(E, gw, gb);

    // GCN layer 0: buf0 -> buf1; layer 1: buf1 -> buf0; layer 2: buf0 -> buf1
    k_agg<<<dim3(128, 8), 256>>>(adj, 0);
    k_combine<<<dim3(N_, 8), 128, CMB_SMEM>>>(0, 0);
    k_agg<<<dim3(128, 8), 256>>>(adj, 1);
    k_combine<<<dim3(N_, 8), 128, CMB_SMEM>>>(1, 1);
    k_agg<<<dim3(128, 8), 256>>>(adj, 0);
    k_combine<<<dim3(N_, 8), 128, CMB_SMEM>>>(0, 2);

    // TCN in-place on buf1, 2 sequences per block
    k_tcn<<<N_ * B_ / 2, 128, TCN_SMEM>>>(tw1, tb1, tw2, tb2, 1);

    // attention layers (in-place on buf1; last writes transposed final output)
    k_attn<<<N_ * B_, 128>>>(awq, awk, awv, awo, ag, ab, 1, nullptr);
    k_attn<<<N_ * B_, 128>>>(awq + 1024, awk + 1024, awv + 1024, awo + 1024,
                             ag + 32, ab + 32, 1, out);
}

// round 7
// speedup vs baseline: 1.8179x; 1.8179x over previous
#include <cuda_runtime.h>
#include <cuda_bf16.h>

#define B_ 4
#define T_ 128
#define N_ 512
#define D_ 32
#define JN_ 16384       // (B*T)*D
#define EMB_ 10

typedef unsigned long long u64;
typedef unsigned int u32;

// ---------------- f32x2 packed helpers (sm_103a FFMA2) -----------------------
__device__ __forceinline__ u64 pack2(float lo, float hi) {
    u64 r; asm("mov.b64 %0, {%1, %2};" : "=l"(r) : "f"(lo), "f"(hi)); return r;
}
__device__ __forceinline__ void unpack2(u64 v, float& lo, float& hi) {
    asm("mov.b64 {%0, %1}, %2;" : "=f"(lo), "=f"(hi) : "l"(v));
}
__device__ __forceinline__ u64 fma2(u64 a, u64 b, u64 c) {
    u64 d; asm("fma.rn.f32x2 %0, %1, %2, %3;" : "=l"(d) : "l"(a), "l"(b), "l"(c)); return d;
}
__device__ __forceinline__ u64 mul2(u64 a, u64 b) {
    u64 d; asm("mul.rn.f32x2 %0, %1, %2;" : "=l"(d) : "l"(a), "l"(b)); return d;
}
__device__ __forceinline__ u64 add2(u64 a, u64 b) {
    u64 d; asm("add.rn.f32x2 %0, %1, %2;" : "=l"(d) : "l"(a), "l"(b)); return d;
}
__device__ __forceinline__ u64 relu2(u64 v) {
    float a, b; unpack2(v, a, b);
    return pack2(fmaxf(a, 0.f), fmaxf(b, 0.f));
}
__device__ __forceinline__ u32 smem_u32(const void* p) {
    u32 a;
    asm("{ .reg .u64 t; cvta.to.shared.u64 t, %1; cvt.u32.u64 %0, t; }"
        : "=r"(a) : "l"(p));
    return a;
}
// ---------------- mma.sync helpers (sm_80+ path, HMMA on sm_103) ------------
__device__ __forceinline__ void ldmx4(u32& r0, u32& r1, u32& r2, u32& r3, u32 a) {
    asm volatile("ldmatrix.sync.aligned.m8n8.x4.shared.b16 {%0,%1,%2,%3}, [%4];"
                 : "=r"(r0), "=r"(r1), "=r"(r2), "=r"(r3) : "r"(a));
}
__device__ __forceinline__ void ldmx4t(u32& r0, u32& r1, u32& r2, u32& r3, u32 a) {
    asm volatile("ldmatrix.sync.aligned.m8n8.x4.trans.shared.b16 {%0,%1,%2,%3}, [%4];"
                 : "=r"(r0), "=r"(r1), "=r"(r2), "=r"(r3) : "r"(a));
}
__device__ __forceinline__ void mma16816(float* c, const u32* a, const u32* b) {
    asm volatile(
        "mma.sync.aligned.m16n8k16.row.col.f32.bf16.bf16.f32 "
        "{%0,%1,%2,%3}, {%4,%5,%6,%7}, {%8,%9}, {%0,%1,%2,%3};"
        : "+f"(c[0]), "+f"(c[1]), "+f"(c[2]), "+f"(c[3])
        : "r"(a[0]), "r"(a[1]), "r"(a[2]), "r"(a[3]), "r"(b[0]), "r"(b[1]));
}

// ---------------- scratch (device globals; no allocations allowed) ----------
__device__ float g_buf0[N_ * JN_];       // layout (n, bt, c), bt = b*T+t
__device__ float g_buf1[N_ * JN_];
__device__ float g_xg[2 * N_ * JN_];     // aggregated supports k=1,2
__device__ float g_S2[N_ * N_];
__device__ float g_W[3 * N_ * 3 * D_ * D_];   // per-layer per-node (k,c,o)
__device__ float g_bias[3 * N_ * D_];
// bf16 2-term splits
__device__ __nv_bfloat16 g_A0[1024 * 512], g_A1[1024 * 512];
__device__ __nv_bfloat16 g_B0[N_ * JN_], g_B1[N_ * JN_];

// ---------------- transpose x (bt,n,c) -> (n,bt,c) --------------------------
__global__ void k_transpose(const float* __restrict__ x) {
    int n = blockIdx.x, bt0 = blockIdx.y * 64, tid = threadIdx.x;
#pragma unroll
    for (int j = 0; j < 8; j++) {
        int idx = j * 256 + tid;
        int r = idx >> 5, c = idx & 31;
        g_buf0[n * JN_ + (bt0 + r) * D_ + c] =
            x[(bt0 + r) * (N_ * D_) + n * D_ + c];
    }
}

// ---------------- S2 = 2*adj@adj - I ----------------------------------------
__global__ void k_s2(const float* __restrict__ A) {
    __shared__ float As[32][33], Bs[32][33];
    int by = blockIdx.y, bx = blockIdx.x, tid = threadIdx.x;
    int ty = tid >> 5, tx = tid & 31;
    float acc[4] = {0.f, 0.f, 0.f, 0.f};
    for (int m0 = 0; m0 < N_; m0 += 32) {
#pragma unroll
        for (int i = 0; i < 4; i++) {
            int r = ty + i * 8;
            As[r][tx] = A[(by * 32 + r) * N_ + m0 + tx];
            Bs[r][tx] = A[(m0 + r) * N_ + bx * 32 + tx];
        }
        __syncthreads();
#pragma unroll
        for (int m = 0; m < 32; m++) {
            float b = Bs[m][tx];
#pragma unroll
            for (int i = 0; i < 4; i++) acc[i] += As[ty + i * 8][m] * b;
        }
        __syncthreads();
    }
#pragma unroll
    for (int i = 0; i < 4; i++) {
        int r = by * 32 + ty + i * 8, c = bx * 32 + tx;
        g_S2[r * N_ + c] = 2.f * acc[i] - (r == c ? 1.f : 0.f);
    }
}

// ---------------- per-node GCN weights --------------------------------------
__global__ void k_wn(const float* __restrict__ E, const float* __restrict__ gw,
                     const float* __restrict__ gb) {
    int n = blockIdx.x, L = blockIdx.y, tid = threadIdx.x;
    float Er[EMB_];
#pragma unroll
    for (int e = 0; e < EMB_; e++) Er[e] = E[n * EMB_ + e];
    const float* g0 = gw + L * (EMB_ * 3072);
    float* wout = g_W + (L * N_ + n) * 3072;
    for (int idx = tid; idx < 3072; idx += 256) {
        float a = 0.f;
#pragma unroll
        for (int e = 0; e < EMB_; e++) a += Er[e] * g0[e * 3072 + idx];
        wout[idx] = a;
    }
    if (tid < 32) {
        const float* b0 = gb + L * (EMB_ * 32);
        float a = 0.f;
#pragma unroll
        for (int e = 0; e < EMB_; e++) a += Er[e] * b0[e * 32 + tid];
        g_bias[(L * N_ + n) * 32 + tid] = a;
    }
}

// ---------------- bf16 2-term split of the [adj;S2] stack -------------------
__global__ void k_prep(const float* __restrict__ adj) {
    int r = blockIdx.x, tid = threadIdx.x;
    const float* src = (r < 512) ? &adj[r * 512] : &g_S2[(r - 512) * 512];
    for (int c = tid; c < 512; c += 256) {
        float v = src[c];
        __nv_bfloat16 h = __float2bfloat16_rn(v);
        float v1 = v - __bfloat162float(h);
        g_A0[r * 512 + c] = h;
        g_A1[r * 512 + c] = __float2bfloat16_rn(v1);
    }
}

// ---------------- bf16 2-term split of H ------------------------------------
__global__ void k_split(int sel) {
    const float* H = sel ? g_buf1 : g_buf0;
    int idx = blockIdx.x * 256 + threadIdx.x;   // float4 index
    float4 v = ((const float4*)H)[idx];
    float vv[4] = {v.x, v.y, v.z, v.w};
    unsigned short hs[4], ms[4];
#pragma unroll
    for (int i = 0; i < 4; i++) {
        __nv_bfloat16 h = __float2bfloat16_rn(vv[i]);
        float r1 = vv[i] - __bfloat162float(h);
        __nv_bfloat16 m = __float2bfloat16_rn(r1);
        hs[i] = __bfloat16_as_ushort(h);
        ms[i] = __bfloat16_as_ushort(m);
    }
    *(uint2*)&g_B0[idx * 4] = make_uint2((u32)hs[0] | ((u32)hs[1] << 16),
                                         (u32)hs[2] | ((u32)hs[3] << 16));
    *(uint2*)&g_B1[idx * 4] = make_uint2((u32)ms[0] | ((u32)ms[1] << 16),
                                         (u32)ms[2] | ((u32)ms[3] << 16));
}

// ---------------- tensor-core aggregation GEMM via mma.sync -----------------
// C[1024,16384] = [adj;S2] @ H ; 3 split products hh+hm+mh accumulated in f32.
// CTA tile 128m x 128j, 8 warps (2m x 4j), warp tile 64m x 32j, K-chunk 32.
#define ASTRIDE 40     // bf16 units; 80B rows (16B aligned)
#define BSTRIDE 136    // bf16 units; 272B rows
__global__ void __launch_bounds__(256) k_aggM() {
    __shared__ __nv_bfloat16 Ah[128 * ASTRIDE], Am[128 * ASTRIDE];
    __shared__ __nv_bfloat16 Bh[32 * BSTRIDE], Bm[32 * BSTRIDE];
    int tid = threadIdx.x, lane = tid & 31, wid = tid >> 5;
    int j0 = blockIdx.x * 128, i0 = blockIdx.y * 128;
    int wm = wid >> 2, wj = wid & 3;
    int lr = lane & 15, lh = lane >> 4;
    float acc[4][4][4];
#pragma unroll
    for (int mt = 0; mt < 4; mt++)
#pragma unroll
        for (int nt = 0; nt < 4; nt++)
#pragma unroll
            for (int q = 0; q < 4; q++) acc[mt][nt][q] = 0.f;

    u32 aBaseH = smem_u32(Ah), aBaseM = smem_u32(Am);
    u32 bBaseH = smem_u32(Bh), bBaseM = smem_u32(Bm);

    for (int k0 = 0; k0 < 512; k0 += 32) {
#pragma unroll
        for (int it = 0; it < 4; it++) {
            int idx = it * 256 + tid;
            int row = idx >> 3, kq = (idx & 7) * 4;
            *(uint2*)&Ah[row * ASTRIDE + kq] =
                *(const uint2*)&g_A0[(i0 + row) * 512 + k0 + kq];
            *(uint2*)&Am[row * ASTRIDE + kq] =
                *(const uint2*)&g_A1[(i0 + row) * 512 + k0 + kq];
        }
#pragma unroll
        for (int it = 0; it < 4; it++) {
            int idx = it * 256 + tid;
            int k = idx >> 5, jq = (idx & 31) * 4;
            *(uint2*)&Bh[k * BSTRIDE + jq] =
                *(const uint2*)&g_B0[(size_t)(k0 + k) * JN_ + j0 + jq];
            *(uint2*)&Bm[k * BSTRIDE + jq] =
                *(const uint2*)&g_B1[(size_t)(k0 + k) * JN_ + j0 + jq];
        }
        __syncthreads();
#pragma unroll
        for (int s2 = 0; s2 < 32; s2 += 16) {
            u32 bh[4][2], bm[4][2];
#pragma unroll
            for (int half = 0; half < 2; half++) {
                u32 boff = (u32)((s2 + lr) * BSTRIDE + wj * 32 + half * 16 + lh * 8) * 2;
                u32 r0, r1, r2, r3;
                ldmx4t(r0, r1, r2, r3, bBaseH + boff);
                bh[half * 2][0] = r0; bh[half * 2][1] = r1;
                bh[half * 2 + 1][0] = r2; bh[half * 2 + 1][1] = r3;
                ldmx4t(r0, r1, r2, r3, bBaseM + boff);
                bm[half * 2][0] = r0; bm[half * 2][1] = r1;
                bm[half * 2 + 1][0] = r2; bm[half * 2 + 1][1] = r3;
            }
#pragma unroll
            for (int mt = 0; mt < 4; mt++) {
                u32 aoff = (u32)((wm * 64 + mt * 16 + lr) * ASTRIDE + s2 + lh * 8) * 2;
                u32 ah[4], am[4];
                ldmx4(ah[0], ah[1], ah[2], ah[3], aBaseH + aoff);
                ldmx4(am[0], am[1], am[2], am[3], aBaseM + aoff);
#pragma unroll
                for (int nt = 0; nt < 4; nt++) {
                    mma16816(acc[mt][nt], ah, bh[nt]);
                    mma16816(acc[mt][nt], ah, bm[nt]);
                    mma16816(acc[mt][nt], am, bh[nt]);
                }
            }
        }
        __syncthreads();
    }
    // epilogue: c0,c1 -> (row = l/4, col = 2(l%4)); c2,c3 -> row+8
    int rbase = i0 + wm * 64 + (lane >> 2);
    int cbase = j0 + wj * 32 + 2 * (lane & 3);
#pragma unroll
    for (int mt = 0; mt < 4; mt++)
#pragma unroll
        for (int nt = 0; nt < 4; nt++) {
            size_t base = (size_t)(rbase + mt * 16) * JN_ + cbase + nt * 8;
            *(float2*)&g_xg[base] = make_float2(acc[mt][nt][0], acc[mt][nt][1]);
            *(float2*)&g_xg[base + 8 * JN_] =
                make_float2(acc[mt][nt][2], acc[mt][nt][3]);
        }
}

// ---------------- combine (R2-proven): out = [H|xg1|xg2] @ W[n] + b[n] ------
__global__ void k_combine(int inSel, int L) {
    __shared__ float Xin[96][68];
    __shared__ float Ws[3072];
    __shared__ float bs[32];
    const float* Hin = inSel ? g_buf1 : g_buf0;
    float* Hout = inSel ? g_buf0 : g_buf1;
    int n = blockIdx.x, bt0 = blockIdx.y * 64, tid = threadIdx.x;
    const float* Wl = g_W + (L * N_ + n) * 3072;
    for (int q = tid; q < 3072; q += 128) Ws[q] = Wl[q];
    if (tid < 32) bs[tid] = g_bias[(L * N_ + n) * 32 + tid];
    const float* s0 = Hin + n * JN_ + bt0 * D_;
    const float* s1 = g_xg + n * JN_ + bt0 * D_;
    const float* s2 = g_xg + (N_ + n) * JN_ + bt0 * D_;
#pragma unroll
    for (int q = tid; q < 2048; q += 128) {
        int r = q >> 5, c = q & 31;
        Xin[c][r] = s0[q];
        Xin[32 + c][r] = s1[q];
        Xin[64 + c][r] = s2[q];
    }
    __syncthreads();
    int to = tid & 7, tb = tid >> 3;
    float acc[4][4];
#pragma unroll
    for (int i = 0; i < 4; i++)
#pragma unroll
        for (int j = 0; j < 4; j++) acc[i][j] = 0.f;
    for (int kc = 0; kc < 96; kc++) {
        float4 xv = *(const float4*)&Xin[kc][tb * 4];
        float4 wv = *(const float4*)&Ws[kc * 32 + to * 4];
        acc[0][0] += xv.x * wv.x; acc[0][1] += xv.x * wv.y;
        acc[0][2] += xv.x * wv.z; acc[0][3] += xv.x * wv.w;
        acc[1][0] += xv.y * wv.x; acc[1][1] += xv.y * wv.y;
        acc[1][2] += xv.y * wv.z; acc[1][3] += xv.y * wv.w;
        acc[2][0] += xv.z * wv.x; acc[2][1] += xv.z * wv.y;
        acc[2][2] += xv.z * wv.z; acc[2][3] += xv.z * wv.w;
        acc[3][0] += xv.w * wv.x; acc[3][1] += xv.w * wv.y;
        acc[3][2] += xv.w * wv.z; acc[3][3] += xv.w * wv.w;
    }
    float4 bv = *(const float4*)&bs[to * 4];
#pragma unroll
    for (int i = 0; i < 4; i++) {
        int bt = bt0 + tb * 4 + i;
        *(float4*)&Hout[n * JN_ + bt * D_ + to * 4] =
            make_float4(acc[i][0] + bv.x, acc[i][1] + bv.y,
                        acc[i][2] + bv.z, acc[i][3] + bv.w);
    }
}

// ---------------- fused TCN: f32x2-packed, 2 sequences per block ------------
#define TCN_SMEM 90880
__global__ void __launch_bounds__(128)
k_tcn(const float* __restrict__ w1, const float* __restrict__ b1,
      const float* __restrict__ w2, const float* __restrict__ b2, int sel) {
    extern __shared__ char dsm[];
    ulonglong2* e01 = (ulonglong2*)dsm;
    u64* wd2 = (u64*)(dsm + 16384);
    u64* bb  = (u64*)(dsm + 16384 + 8192);
    u64 (*y0)[129] = (u64(*)[129])(dsm + 24832);
    u64 (*y1)[129] = (u64(*)[129])(dsm + 24832 + 33024);

    float* base = sel ? g_buf1 : g_buf0;
    float* seqA = base + (2 * blockIdx.x) * 4096;
    float* seqB = seqA + 4096;
    int t = threadIdx.x;

#pragma unroll
    for (int j = 0; j < 32; j++) {
        int idx = j * 128 + t;
        int c = idx & 31, tt = idx >> 5;
        y0[c][tt] = pack2(seqA[idx], seqB[idx]);
    }
    for (int blk = 0; blk < 3; blk++) {
        int dil = 1 << blk;
        __syncthreads();
        const float* ws = w1 + blk * 3072;
        for (int q = t; q < 1024; q += 128) {
            float a = ws[q * 3], b = ws[q * 3 + 1], c = ws[q * 3 + 2];
            e01[q] = make_ulonglong2(pack2(a, a), pack2(b, b));
            wd2[q] = pack2(c, c);
        }
        if (t < 32) { float v = b1[blk * 32 + t]; bb[t] = pack2(v, v); }
        __syncthreads();
        u64 acc[32];
#pragma unroll
        for (int o = 0; o < 32; o++) acc[o] = bb[o];
        for (int c = 0; c < 32; c++) {
            u64 i0 = (t >= 2 * dil) ? y0[c][t - 2 * dil] : 0ULL;
            u64 i1 = (t >= dil) ? y0[c][t - dil] : 0ULL;
            u64 i2 = y0[c][t];
#pragma unroll
            for (int o = 0; o < 32; o++) {
                ulonglong2 w01 = e01[o * 32 + c];
                acc[o] = fma2(w01.x, i0, acc[o]);
                acc[o] = fma2(w01.y, i1, acc[o]);
                acc[o] = fma2(wd2[o * 32 + c], i2, acc[o]);
            }
        }
#pragma unroll
        for (int o = 0; o < 32; o++) y1[o][t] = relu2(acc[o]);
        __syncthreads();
        const float* ws2 = w2 + blk * 3072;
        for (int q = t; q < 1024; q += 128) {
            float a = ws2[q * 3], b = ws2[q * 3 + 1], c = ws2[q * 3 + 2];
            e01[q] = make_ulonglong2(pack2(a, a), pack2(b, b));
            wd2[q] = pack2(c, c);
        }
        if (t < 32) { float v = b2[blk * 32 + t]; bb[t] = pack2(v, v); }
        __syncthreads();
#pragma unroll
        for (int o = 0; o < 32; o++) acc[o] = bb[o];
        for (int c = 0; c < 32; c++) {
            u64 i0 = (t >= 2 * dil) ? y1[c][t - 2 * dil] : 0ULL;
            u64 i1 = (t >= dil) ? y1[c][t - dil] : 0ULL;
            u64 i2 = y1[c][t];
#pragma unroll
            for (int o = 0; o < 32; o++) {
                ulonglong2 w01 = e01[o * 32 + c];
                acc[o] = fma2(w01.x, i0, acc[o]);
                acc[o] = fma2(w01.y, i1, acc[o]);
                acc[o] = fma2(wd2[o * 32 + c], i2, acc[o]);
            }
        }
#pragma unroll
        for (int o = 0; o < 32; o++)
            y0[o][t] = relu2(add2(relu2(acc[o]), y0[o][t]));
    }
    __syncthreads();
#pragma unroll
    for (int j = 0; j < 32; j++) {
        int idx = j * 128 + t;
        int c = idx & 31, tt = idx >> 5;
        float lo, hi; unpack2(y0[c][tt], lo, hi);
        seqA[idx] = lo; seqB[idx] = hi;
    }
}

// ---------------- temporal attention + layernorm, f32x2 head-packed ---------
__global__ void __launch_bounds__(128)
k_attn(const float* __restrict__ wq, const float* __restrict__ wk,
       const float* __restrict__ wv, const float* __restrict__ wo,
       const float* __restrict__ gga, const float* __restrict__ bba,
       int sel, float* __restrict__ finalOut) {
    __shared__ ulonglong2 Kp[128][8];
    __shared__ ulonglong2 Vp[128][8];
    __shared__ ulonglong2 Wq2[32][8];
    __shared__ ulonglong2 Wk2[32][8];
    __shared__ ulonglong2 Wv2[32][8];
    __shared__ float gs[32], bs2[32];
    float* seq = (sel ? g_buf1 : g_buf0) + blockIdx.x * 4096;
    int t = threadIdx.x;

    u64* Wq2u = (u64*)Wq2; u64* Wk2u = (u64*)Wk2; u64* Wv2u = (u64*)Wv2;
    for (int idx = t; idx < 512; idx += 128) {
        int c = idx >> 4, d = idx & 15;
        Wq2u[c * 16 + d] = pack2(wq[c * 32 + d], wq[c * 32 + d + 16]);
        Wk2u[c * 16 + d] = pack2(wk[c * 32 + d], wk[c * 32 + d + 16]);
        Wv2u[c * 16 + d] = pack2(wv[c * 32 + d], wv[c * 32 + d + 16]);
    }
    if (t < 32) { gs[t] = gga[t]; bs2[t] = bba[t]; }
    __syncthreads();

    float hrow[32];
#pragma unroll
    for (int o4 = 0; o4 < 8; o4++)
        *(float4*)&hrow[o4 * 4] = *(const float4*)&seq[t * 32 + o4 * 4];

    u64 qp[16], tv[16];
#pragma unroll
    for (int d = 0; d < 16; d++) qp[d] = 0ULL;
    for (int c = 0; c < 32; c++) {
        u64 hd = pack2(hrow[c], hrow[c]);
#pragma unroll
        for (int j = 0; j < 8; j++) {
            ulonglong2 w = Wq2[c][j];
            qp[2 * j] = fma2(w.x, hd, qp[2 * j]);
            qp[2 * j + 1] = fma2(w.y, hd, qp[2 * j + 1]);
        }
    }
    u64 qsc = pack2(0.25f, 0.25f);
#pragma unroll
    for (int d = 0; d < 16; d++) qp[d] = mul2(qp[d], qsc);

#pragma unroll
    for (int d = 0; d < 16; d++) tv[d] = 0ULL;
    for (int c = 0; c < 32; c++) {
        u64 hd = pack2(hrow[c], hrow[c]);
#pragma unroll
        for (int j = 0; j < 8; j++) {
            ulonglong2 w = Wk2[c][j];
            tv[2 * j] = fma2(w.x, hd, tv[2 * j]);
            tv[2 * j + 1] = fma2(w.y, hd, tv[2 * j + 1]);
        }
    }
#pragma unroll
    for (int j = 0; j < 8; j++) Kp[t][j] = make_ulonglong2(tv[2 * j], tv[2 * j + 1]);

#pragma unroll
    for (int d = 0; d < 16; d++) tv[d] = 0ULL;
    for (int c = 0; c < 32; c++) {
        u64 hd = pack2(hrow[c], hrow[c]);
#pragma unroll
        for (int j = 0; j < 8; j++) {
            ulonglong2 w = Wv2[c][j];
            tv[2 * j] = fma2(w.x, hd, tv[2 * j]);
            tv[2 * j + 1] = fma2(w.y, hd, tv[2 * j + 1]);
        }
    }
#pragma unroll
    for (int j = 0; j < 8; j++) Vp[t][j] = make_ulonglong2(tv[2 * j], tv[2 * j + 1]);
    __syncthreads();
    for (int idx = t; idx < 512; idx += 128) {
        int c = idx >> 4, d = idx & 15;
        Wq2u[c * 16 + d] = pack2(wo[c * 32 + d], wo[c * 32 + d + 16]);
    }

    float m0 = -3e38f, l0 = 0.f, m1 = -3e38f, l1 = 0.f;
    u64 acc[16];
#pragma unroll
    for (int d = 0; d < 16; d++) acc[d] = 0ULL;
    for (int kp = 0; kp < 128; kp++) {
        u64 s = 0ULL;
#pragma unroll
        for (int j = 0; j < 8; j++) {
            ulonglong2 k2 = Kp[kp][j];
            s = fma2(qp[2 * j], k2.x, s);
            s = fma2(qp[2 * j + 1], k2.y, s);
        }
        float s0, s1; unpack2(s, s0, s1);
        float nm0 = fmaxf(m0, s0), nm1 = fmaxf(m1, s1);
        float cf0 = __expf(m0 - nm0), cf1 = __expf(m1 - nm1);
        float p0 = __expf(s0 - nm0), p1 = __expf(s1 - nm1);
        l0 = l0 * cf0 + p0; l1 = l1 * cf1 + p1;
        m0 = nm0; m1 = nm1;
        u64 cfp = pack2(cf0, cf1), pp = pack2(p0, p1);
#pragma unroll
        for (int j = 0; j < 8; j++) {
            ulonglong2 v2 = Vp[kp][j];
            acc[2 * j] = fma2(acc[2 * j], cfp, mul2(pp, v2.x));
            acc[2 * j + 1] = fma2(acc[2 * j + 1], cfp, mul2(pp, v2.y));
        }
    }
    u64 inv = pack2(1.f / l0, 1.f / l1);
    float ov[32];
#pragma unroll
    for (int d = 0; d < 16; d++) {
        u64 a = mul2(acc[d], inv);
        unpack2(a, ov[d], ov[d + 16]);
    }
    __syncthreads();

    u64 rp[16];
#pragma unroll
    for (int d = 0; d < 16; d++)
        rp[d] = pack2(seq[t * 32 + d], seq[t * 32 + d + 16]);
    for (int c = 0; c < 32; c++) {
        u64 od = pack2(ov[c], ov[c]);
#pragma unroll
        for (int j = 0; j < 8; j++) {
            ulonglong2 w = Wq2[c][j];
            rp[2 * j] = fma2(w.x, od, rp[2 * j]);
            rp[2 * j + 1] = fma2(w.y, od, rp[2 * j + 1]);
        }
    }
    float r[32];
#pragma unroll
    for (int d = 0; d < 16; d++) unpack2(rp[d], r[d], r[d + 16]);
    float mu = 0.f;
#pragma unroll
    for (int o = 0; o < 32; o++) mu += r[o];
    mu *= (1.f / 32.f);
    float var = 0.f;
#pragma unroll
    for (int o = 0; o < 32; o++) { float d = r[o] - mu; var += d * d; }
    var *= (1.f / 32.f);
    float rs = rsqrtf(var + 1e-5f);
#pragma unroll
    for (int o = 0; o < 32; o++) r[o] = (r[o] - mu) * rs * gs[o] + bs2[o];

    if (finalOut == nullptr) {
#pragma unroll
        for (int o4 = 0; o4 < 8; o4++)
            *(float4*)&seq[t * 32 + o4 * 4] =
                make_float4(r[o4 * 4], r[o4 * 4 + 1], r[o4 * 4 + 2], r[o4 * 4 + 3]);
    } else {
        int n = blockIdx.x >> 2, b = blockIdx.x & 3;
        float* dst = finalOut + ((b * T_ + t) * N_ + n) * D_;
#pragma unroll
        for (int o4 = 0; o4 < 8; o4++)
            *(float4*)&dst[o4 * 4] =
                make_float4(r[o4 * 4], r[o4 * 4 + 1], r[o4 * 4 + 2], r[o4 * 4 + 3]);
    }
}

// ---------------- launcher ---------------------------------------------------
extern "C" void kernel_launch(void* const* d_in, const int* in_sizes, int n_in,
                              void* d_out, int out_size) {
    (void)in_sizes; (void)n_in; (void)out_size;
    const float* x   = (const float*)d_in[0];
    const float* E   = (const float*)d_in[2];
    const float* adj = (const float*)d_in[3];
    const float* gw  = (const float*)d_in[4];
    const float* gb  = (const float*)d_in[5];
    const float* tw1 = (const float*)d_in[6];
    const float* tb1 = (const float*)d_in[7];
    const float* tw2 = (const float*)d_in[8];
    const float* tb2 = (const float*)d_in[9];
    const float* awq = (const float*)d_in[10];
    const float* awk = (const float*)d_in[11];
    const float* awv = (const float*)d_in[12];
    const float* awo = (const float*)d_in[13];
    const float* ag  = (const float*)d_in[14];
    const float* ab  = (const float*)d_in[15];
    float* out = (float*)d_out;

    cudaFuncSetAttribute(k_tcn, cudaFuncAttributeMaxDynamicSharedMemorySize,
                         TCN_SMEM);

    k_transpose<<<dim3(N_, 8), 256>>>(x);
    k_s2<<<dim3(16, 16), 256>>>(adj);
    k_wn<<<dim3(N_, 3), 256>>>(E, gw, gb);
    k_prep<<<1024, 256>>>(adj);

    // GCN layer 0: buf0 -> buf1; layer 1: buf1 -> buf0; layer 2: buf0 -> buf1
    k_split<<<8192, 256>>>(0);
    k_aggM<<<dim3(128, 8), 256>>>();
    k_combine<<<dim3(N_, 8), 128>>>(0, 0);
    k_split<<<8192, 256>>>(1);
    k_aggM<<<dim3(128, 8), 256>>>();
    k_combine<<<dim3(N_, 8), 128>>>(1, 1);
    k_split<<<8192, 256>>>(0);
    k_aggM<<<dim3(128, 8), 256>>>();
    k_combine<<<dim3(N_, 8), 128>>>(0, 2);

    // TCN in-place on buf1, 2 sequences per block
    k_tcn<<<N_ * B_ / 2, 128, TCN_SMEM>>>(tw1, tb1, tw2, tb2, 1);

    // attention layers (in-place on buf1; last writes transposed final output)
    k_attn<<<N_ * B_, 128>>>(awq, awk, awv, awo, ag, ab, 1, nullptr);
    k_attn<<<N_ * B_, 128>>>(awq + 1024, awk + 1024, awv + 1024, awo + 1024,
                             ag + 32, ab + 32, 1, out);
}

// round 8
// speedup vs baseline: 1.8344x; 1.0091x over previous
#include <cuda_runtime.h>
#include <cuda_bf16.h>

#define B_ 4
#define T_ 128
#define N_ 512
#define D_ 32
#define JN_ 16384       // (B*T)*D
#define EMB_ 10

typedef unsigned long long u64;
typedef unsigned int u32;

// ---------------- f32x2 packed helpers (sm_103a FFMA2) -----------------------
__device__ __forceinline__ u64 pack2(float lo, float hi) {
    u64 r; asm("mov.b64 %0, {%1, %2};" : "=l"(r) : "f"(lo), "f"(hi)); return r;
}
__device__ __forceinline__ void unpack2(u64 v, float& lo, float& hi) {
    asm("mov.b64 {%0, %1}, %2;" : "=f"(lo), "=f"(hi) : "l"(v));
}
__device__ __forceinline__ u64 fma2(u64 a, u64 b, u64 c) {
    u64 d; asm("fma.rn.f32x2 %0, %1, %2, %3;" : "=l"(d) : "l"(a), "l"(b), "l"(c)); return d;
}
__device__ __forceinline__ u64 mul2(u64 a, u64 b) {
    u64 d; asm("mul.rn.f32x2 %0, %1, %2;" : "=l"(d) : "l"(a), "l"(b)); return d;
}
__device__ __forceinline__ u64 add2(u64 a, u64 b) {
    u64 d; asm("add.rn.f32x2 %0, %1, %2;" : "=l"(d) : "l"(a), "l"(b)); return d;
}
__device__ __forceinline__ u64 relu2(u64 v) {
    float a, b; unpack2(v, a, b);
    return pack2(fmaxf(a, 0.f), fmaxf(b, 0.f));
}
__device__ __forceinline__ u32 smem_u32(const void* p) {
    u32 a;
    asm("{ .reg .u64 t; cvta.to.shared.u64 t, %1; cvt.u32.u64 %0, t; }"
        : "=r"(a) : "l"(p));
    return a;
}
// ---------------- mma.sync helpers (sm_80+ path, HMMA on sm_103) ------------
__device__ __forceinline__ void ldmx4(u32& r0, u32& r1, u32& r2, u32& r3, u32 a) {
    asm volatile("ldmatrix.sync.aligned.m8n8.x4.shared.b16 {%0,%1,%2,%3}, [%4];"
                 : "=r"(r0), "=r"(r1), "=r"(r2), "=r"(r3) : "r"(a));
}
__device__ __forceinline__ void ldmx4t(u32& r0, u32& r1, u32& r2, u32& r3, u32 a) {
    asm volatile("ldmatrix.sync.aligned.m8n8.x4.trans.shared.b16 {%0,%1,%2,%3}, [%4];"
                 : "=r"(r0), "=r"(r1), "=r"(r2), "=r"(r3) : "r"(a));
}
__device__ __forceinline__ void mma16816(float* c, const u32* a, const u32* b) {
    asm volatile(
        "mma.sync.aligned.m16n8k16.row.col.f32.bf16.bf16.f32 "
        "{%0,%1,%2,%3}, {%4,%5,%6,%7}, {%8,%9}, {%0,%1,%2,%3};"
        : "+f"(c[0]), "+f"(c[1]), "+f"(c[2]), "+f"(c[3])
        : "r"(a[0]), "r"(a[1]), "r"(a[2]), "r"(a[3]), "r"(b[0]), "r"(b[1]));
}
__device__ __forceinline__ void cpa16(u32 dst, const void* src) {
    asm volatile("cp.async.cg.shared.global [%0], [%1], 16;"
                 :: "r"(dst), "l"(src));
}

// ---------------- scratch (device globals; no allocations allowed) ----------
__device__ float g_buf0[N_ * JN_];       // layout (n, bt, c), bt = b*T+t
__device__ float g_buf1[N_ * JN_];
__device__ float g_xg[2 * N_ * JN_];     // aggregated supports k=1,2
__device__ float g_S2[N_ * N_];
__device__ float g_W[3 * N_ * 3 * D_ * D_];   // per-layer per-node (k,c,o)
__device__ float g_bias[3 * N_ * D_];
// bf16 2-term splits
__device__ __nv_bfloat16 g_A0[1024 * 512], g_A1[1024 * 512];
__device__ __nv_bfloat16 g_B0[N_ * JN_], g_B1[N_ * JN_];

// ---------------- transpose x (bt,n,c) -> (n,bt,c), fused bf16 split --------
__global__ void k_transpose(const float* __restrict__ x) {
    int n = blockIdx.x, bt0 = blockIdx.y * 64, tid = threadIdx.x;
#pragma unroll
    for (int j = 0; j < 8; j++) {
        int idx = j * 256 + tid;
        int r = idx >> 5, c = idx & 31;
        float v = x[(bt0 + r) * (N_ * D_) + n * D_ + c];
        int di = n * JN_ + (bt0 + r) * D_ + c;
        g_buf0[di] = v;
        __nv_bfloat16 h = __float2bfloat16_rn(v);
        g_B0[di] = h;
        g_B1[di] = __float2bfloat16_rn(v - __bfloat162float(h));
    }
}

// ---------------- S2 = 2*adj@adj - I ----------------------------------------
__global__ void k_s2(const float* __restrict__ A) {
    __shared__ float As[32][33], Bs[32][33];
    int by = blockIdx.y, bx = blockIdx.x, tid = threadIdx.x;
    int ty = tid >> 5, tx = tid & 31;
    float acc[4] = {0.f, 0.f, 0.f, 0.f};
    for (int m0 = 0; m0 < N_; m0 += 32) {
#pragma unroll
        for (int i = 0; i < 4; i++) {
            int r = ty + i * 8;
            As[r][tx] = A[(by * 32 + r) * N_ + m0 + tx];
            Bs[r][tx] = A[(m0 + r) * N_ + bx * 32 + tx];
        }
        __syncthreads();
#pragma unroll
        for (int m = 0; m < 32; m++) {
            float b = Bs[m][tx];
#pragma unroll
            for (int i = 0; i < 4; i++) acc[i] += As[ty + i * 8][m] * b;
        }
        __syncthreads();
    }
#pragma unroll
    for (int i = 0; i < 4; i++) {
        int r = by * 32 + ty + i * 8, c = bx * 32 + tx;
        g_S2[r * N_ + c] = 2.f * acc[i] - (r == c ? 1.f : 0.f);
    }
}

// ---------------- per-node GCN weights --------------------------------------
__global__ void k_wn(const float* __restrict__ E, const float* __restrict__ gw,
                     const float* __restrict__ gb) {
    int n = blockIdx.x, L = blockIdx.y, tid = threadIdx.x;
    float Er[EMB_];
#pragma unroll
    for (int e = 0; e < EMB_; e++) Er[e] = E[n * EMB_ + e];
    const float* g0 = gw + L * (EMB_ * 3072);
    float* wout = g_W + (L * N_ + n) * 3072;
    for (int idx = tid; idx < 3072; idx += 256) {
        float a = 0.f;
#pragma unroll
        for (int e = 0; e < EMB_; e++) a += Er[e] * g0[e * 3072 + idx];
        wout[idx] = a;
    }
    if (tid < 32) {
        const float* b0 = gb + L * (EMB_ * 32);
        float a = 0.f;
#pragma unroll
        for (int e = 0; e < EMB_; e++) a += Er[e] * b0[e * 32 + tid];
        g_bias[(L * N_ + n) * 32 + tid] = a;
    }
}

// ---------------- bf16 2-term split of the [adj;S2] stack -------------------
__global__ void k_prep(const float* __restrict__ adj) {
    int r = blockIdx.x, tid = threadIdx.x;
    const float* src = (r < 512) ? &adj[r * 512] : &g_S2[(r - 512) * 512];
    for (int c = tid; c < 512; c += 256) {
        float v = src[c];
        __nv_bfloat16 h = __float2bfloat16_rn(v);
        float v1 = v - __bfloat162float(h);
        g_A0[r * 512 + c] = h;
        g_A1[r * 512 + c] = __float2bfloat16_rn(v1);
    }
}

// ---------------- tensor-core aggregation GEMM via mma.sync -----------------
// C[1024,16384] = [adj;S2] @ H ; 3 split products hh+hm+mh accumulated in f32.
// CTA tile 128m x 128j, 8 warps (2m x 4j), K-chunk 32, cp.async double buffer.
// Stage layout (bytes): Ah[0,10240) Am[10240,20480) Bh[20480,29184) Bm[29184,37888)
#define AGG_STAGE 37888
#define AGG_SMEM (2 * AGG_STAGE)    // 75776
__global__ void __launch_bounds__(256) k_aggM() {
    extern __shared__ char smdyn[];
    u32 sbase = smem_u32(smdyn);
    int tid = threadIdx.x, lane = tid & 31, wid = tid >> 5;
    int j0 = blockIdx.x * 128, i0 = blockIdx.y * 128;
    int wm = wid >> 2, wj = wid & 3;
    int lr = lane & 15, lh = lane >> 4;
    float acc[4][4][4];
#pragma unroll
    for (int mt = 0; mt < 4; mt++)
#pragma unroll
        for (int nt = 0; nt < 4; nt++)
#pragma unroll
            for (int q = 0; q < 4; q++) acc[mt][nt][q] = 0.f;

    auto loadStage = [&](int ch, int st) {
        u32 sb = sbase + st * AGG_STAGE;
        int k0 = ch * 32;
#pragma unroll
        for (int it = 0; it < 2; it++) {
            int idx = it * 256 + tid;
            int row = idx >> 2, c16 = idx & 3;
            cpa16(sb + row * 80 + c16 * 16,
                  &g_A0[(i0 + row) * 512 + k0 + c16 * 8]);
            cpa16(sb + 10240 + row * 80 + c16 * 16,
                  &g_A1[(i0 + row) * 512 + k0 + c16 * 8]);
        }
#pragma unroll
        for (int it = 0; it < 2; it++) {
            int idx = it * 256 + tid;
            int k = idx >> 4, c = idx & 15;
            cpa16(sb + 20480 + k * 272 + c * 16,
                  &g_B0[(size_t)(k0 + k) * JN_ + j0 + c * 8]);
            cpa16(sb + 29184 + k * 272 + c * 16,
                  &g_B1[(size_t)(k0 + k) * JN_ + j0 + c * 8]);
        }
        asm volatile("cp.async.commit_group;" ::: "memory");
    };

    loadStage(0, 0);
    for (int ch = 0; ch < 16; ch++) {
        if (ch + 1 < 16) {
            loadStage(ch + 1, (ch + 1) & 1);
            asm volatile("cp.async.wait_group 1;" ::: "memory");
        } else {
            asm volatile("cp.async.wait_group 0;" ::: "memory");
        }
        __syncthreads();
        u32 sb = sbase + (ch & 1) * AGG_STAGE;
        u32 aH = sb, aM = sb + 10240, bH = sb + 20480, bM = sb + 29184;
#pragma unroll
        for (int s2 = 0; s2 < 32; s2 += 16) {
            u32 bh[4][2], bm[4][2];
#pragma unroll
            for (int half = 0; half < 2; half++) {
                u32 boff = (u32)((s2 + lr) * 272 +
                                 (wj * 32 + half * 16 + lh * 8) * 2);
                u32 r0, r1, r2, r3;
                ldmx4t(r0, r1, r2, r3, bH + boff);
                bh[half * 2][0] = r0; bh[half * 2][1] = r1;
                bh[half * 2 + 1][0] = r2; bh[half * 2 + 1][1] = r3;
                ldmx4t(r0, r1, r2, r3, bM + boff);
                bm[half * 2][0] = r0; bm[half * 2][1] = r1;
                bm[half * 2 + 1][0] = r2; bm[half * 2 + 1][1] = r3;
            }
#pragma unroll
            for (int mt = 0; mt < 4; mt++) {
                u32 aoff = (u32)((wm * 64 + mt * 16 + lr) * 80 +
                                 (s2 + lh * 8) * 2);
                u32 ah[4], am[4];
                ldmx4(ah[0], ah[1], ah[2], ah[3], aH + aoff);
                ldmx4(am[0], am[1], am[2], am[3], aM + aoff);
#pragma unroll
                for (int nt = 0; nt < 4; nt++) {
                    mma16816(acc[mt][nt], ah, bh[nt]);
                    mma16816(acc[mt][nt], ah, bm[nt]);
                    mma16816(acc[mt][nt], am, bh[nt]);
                }
            }
        }
        __syncthreads();
    }
    // epilogue: c0,c1 -> (row = l/4, col = 2(l%4)); c2,c3 -> row+8
    int rbase = i0 + wm * 64 + (lane >> 2);
    int cbase = j0 + wj * 32 + 2 * (lane & 3);
#pragma unroll
    for (int mt = 0; mt < 4; mt++)
#pragma unroll
        for (int nt = 0; nt < 4; nt++) {
            size_t base = (size_t)(rbase + mt * 16) * JN_ + cbase + nt * 8;
            *(float2*)&g_xg[base] = make_float2(acc[mt][nt][0], acc[mt][nt][1]);
            *(float2*)&g_xg[base + 8 * JN_] =
                make_float2(acc[mt][nt][2], acc[mt][nt][3]);
        }
}

// ---------------- combine: out = [H|xg1|xg2] @ W[n] + b[n], fused split -----
__global__ void k_combine(int inSel, int L, int doSplit) {
    __shared__ float Xin[96][68];
    __shared__ float Ws[3072];
    __shared__ float bs[32];
    const float* Hin = inSel ? g_buf1 : g_buf0;
    float* Hout = inSel ? g_buf0 : g_buf1;
    int n = blockIdx.x, bt0 = blockIdx.y * 64, tid = threadIdx.x;
    const float* Wl = g_W + (L * N_ + n) * 3072;
    for (int q = tid; q < 3072; q += 128) Ws[q] = Wl[q];
    if (tid < 32) bs[tid] = g_bias[(L * N_ + n) * 32 + tid];
    const float* s0 = Hin + n * JN_ + bt0 * D_;
    const float* s1 = g_xg + n * JN_ + bt0 * D_;
    const float* s2 = g_xg + (N_ + n) * JN_ + bt0 * D_;
#pragma unroll
    for (int q = tid; q < 2048; q += 128) {
        int r = q >> 5, c = q & 31;
        Xin[c][r] = s0[q];
        Xin[32 + c][r] = s1[q];
        Xin[64 + c][r] = s2[q];
    }
    __syncthreads();
    int to = tid & 7, tb = tid >> 3;
    float acc[4][4];
#pragma unroll
    for (int i = 0; i < 4; i++)
#pragma unroll
        for (int j = 0; j < 4; j++) acc[i][j] = 0.f;
    for (int kc = 0; kc < 96; kc++) {
        float4 xv = *(const float4*)&Xin[kc][tb * 4];
        float4 wv = *(const float4*)&Ws[kc * 32 + to * 4];
        acc[0][0] += xv.x * wv.x; acc[0][1] += xv.x * wv.y;
        acc[0][2] += xv.x * wv.z; acc[0][3] += xv.x * wv.w;
        acc[1][0] += xv.y * wv.x; acc[1][1] += xv.y * wv.y;
        acc[1][2] += xv.y * wv.z; acc[1][3] += xv.y * wv.w;
        acc[2][0] += xv.z * wv.x; acc[2][1] += xv.z * wv.y;
        acc[2][2] += xv.z * wv.z; acc[2][3] += xv.z * wv.w;
        acc[3][0] += xv.w * wv.x; acc[3][1] += xv.w * wv.y;
        acc[3][2] += xv.w * wv.z; acc[3][3] += xv.w * wv.w;
    }
    float4 bv = *(const float4*)&bs[to * 4];
#pragma unroll
    for (int i = 0; i < 4; i++) {
        int bt = bt0 + tb * 4 + i;
        float o0 = acc[i][0] + bv.x, o1 = acc[i][1] + bv.y;
        float o2 = acc[i][2] + bv.z, o3 = acc[i][3] + bv.w;
        int di = n * JN_ + bt * D_ + to * 4;
        *(float4*)&Hout[di] = make_float4(o0, o1, o2, o3);
        if (doSplit) {
            float vv[4] = {o0, o1, o2, o3};
            unsigned short hs[4], ms[4];
#pragma unroll
            for (int q = 0; q < 4; q++) {
                __nv_bfloat16 h = __float2bfloat16_rn(vv[q]);
                hs[q] = __bfloat16_as_ushort(h);
                ms[q] = __bfloat16_as_ushort(
                    __float2bfloat16_rn(vv[q] - __bfloat162float(h)));
            }
            *(uint2*)&g_B0[di] = make_uint2((u32)hs[0] | ((u32)hs[1] << 16),
                                            (u32)hs[2] | ((u32)hs[3] << 16));
            *(uint2*)&g_B1[di] = make_uint2((u32)ms[0] | ((u32)ms[1] << 16),
                                            (u32)ms[2] | ((u32)ms[3] << 16));
        }
    }
}

// ---------------- fused TCN: f32x2-packed, 2 sequences per block ------------
#define TCN_SMEM 90880
__global__ void __launch_bounds__(128)
k_tcn(const float* __restrict__ w1, const float* __restrict__ b1,
      const float* __restrict__ w2, const float* __restrict__ b2, int sel) {
    extern __shared__ char dsm[];
    ulonglong2* e01 = (ulonglong2*)dsm;
    u64* wd2 = (u64*)(dsm + 16384);
    u64* bb  = (u64*)(dsm + 16384 + 8192);
    u64 (*y0)[129] = (u64(*)[129])(dsm + 24832);
    u64 (*y1)[129] = (u64(*)[129])(dsm + 24832 + 33024);

    float* base = sel ? g_buf1 : g_buf0;
    float* seqA = base + (2 * blockIdx.x) * 4096;
    float* seqB = seqA + 4096;
    int t = threadIdx.x;

#pragma unroll
    for (int j = 0; j < 32; j++) {
        int idx = j * 128 + t;
        int c = idx & 31, tt = idx >> 5;
        y0[c][tt] = pack2(seqA[idx], seqB[idx]);
    }
    for (int blk = 0; blk < 3; blk++) {
        int dil = 1 << blk;
        __syncthreads();
        const float* ws = w1 + blk * 3072;
        for (int q = t; q < 1024; q += 128) {
            float a = ws[q * 3], b = ws[q * 3 + 1], c = ws[q * 3 + 2];
            e01[q] = make_ulonglong2(pack2(a, a), pack2(b, b));
            wd2[q] = pack2(c, c);
        }
        if (t < 32) { float v = b1[blk * 32 + t]; bb[t] = pack2(v, v); }
        __syncthreads();
        u64 acc[32];
#pragma unroll
        for (int o = 0; o < 32; o++) acc[o] = bb[o];
        for (int c = 0; c < 32; c++) {
            u64 i0 = (t >= 2 * dil) ? y0[c][t - 2 * dil] : 0ULL;
            u64 i1 = (t >= dil) ? y0[c][t - dil] : 0ULL;
            u64 i2 = y0[c][t];
#pragma unroll
            for (int o = 0; o < 32; o++) {
                ulonglong2 w01 = e01[o * 32 + c];
                acc[o] = fma2(w01.x, i0, acc[o]);
                acc[o] = fma2(w01.y, i1, acc[o]);
                acc[o] = fma2(wd2[o * 32 + c], i2, acc[o]);
            }
        }
#pragma unroll
        for (int o = 0; o < 32; o++) y1[o][t] = relu2(acc[o]);
        __syncthreads();
        const float* ws2 = w2 + blk * 3072;
        for (int q = t; q < 1024; q += 128) {
            float a = ws2[q * 3], b = ws2[q * 3 + 1], c = ws2[q * 3 + 2];
            e01[q] = make_ulonglong2(pack2(a, a), pack2(b, b));
            wd2[q] = pack2(c, c);
        }
        if (t < 32) { float v = b2[blk * 32 + t]; bb[t] = pack2(v, v); }
        __syncthreads();
#pragma unroll
        for (int o = 0; o < 32; o++) acc[o] = bb[o];
        for (int c = 0; c < 32; c++) {
            u64 i0 = (t >= 2 * dil) ? y1[c][t - 2 * dil] : 0ULL;
            u64 i1 = (t >= dil) ? y1[c][t - dil] : 0ULL;
            u64 i2 = y1[c][t];
#pragma unroll
            for (int o = 0; o < 32; o++) {
                ulonglong2 w01 = e01[o * 32 + c];
                acc[o] = fma2(w01.x, i0, acc[o]);
                acc[o] = fma2(w01.y, i1, acc[o]);
                acc[o] = fma2(wd2[o * 32 + c], i2, acc[o]);
            }
        }
#pragma unroll
        for (int o = 0; o < 32; o++)
            y0[o][t] = relu2(add2(relu2(acc[o]), y0[o][t]));
    }
    __syncthreads();
#pragma unroll
    for (int j = 0; j < 32; j++) {
        int idx = j * 128 + t;
        int c = idx & 31, tt = idx >> 5;
        float lo, hi; unpack2(y0[c][tt], lo, hi);
        seqA[idx] = lo; seqB[idx] = hi;
    }
}

// ---------------- temporal attention + layernorm, f32x2 head-packed ---------
__global__ void __launch_bounds__(128)
k_attn(const float* __restrict__ wq, const float* __restrict__ wk,
       const float* __restrict__ wv, const float* __restrict__ wo,
       const float* __restrict__ gga, const float* __restrict__ bba,
       int sel, float* __restrict__ finalOut) {
    __shared__ ulonglong2 Kp[128][8];
    __shared__ ulonglong2 Vp[128][8];
    __shared__ ulonglong2 Wq2[32][8];
    __shared__ ulonglong2 Wk2[32][8];
    __shared__ ulonglong2 Wv2[32][8];
    __shared__ float gs[32], bs2[32];
    float* seq = (sel ? g_buf1 : g_buf0) + blockIdx.x * 4096;
    int t = threadIdx.x;

    u64* Wq2u = (u64*)Wq2; u64* Wk2u = (u64*)Wk2; u64* Wv2u = (u64*)Wv2;
    for (int idx = t; idx < 512; idx += 128) {
        int c = idx >> 4, d = idx & 15;
        Wq2u[c * 16 + d] = pack2(wq[c * 32 + d], wq[c * 32 + d + 16]);
        Wk2u[c * 16 + d] = pack2(wk[c * 32 + d], wk[c * 32 + d + 16]);
        Wv2u[c * 16 + d] = pack2(wv[c * 32 + d], wv[c * 32 + d + 16]);
    }
    if (t < 32) { gs[t] = gga[t]; bs2[t] = bba[t]; }
    __syncthreads();

    float hrow[32];
#pragma unroll
    for (int o4 = 0; o4 < 8; o4++)
        *(float4*)&hrow[o4 * 4] = *(const float4*)&seq[t * 32 + o4 * 4];

    u64 qp[16], tv[16];
#pragma unroll
    for (int d = 0; d < 16; d++) qp[d] = 0ULL;
    for (int c = 0; c < 32; c++) {
        u64 hd = pack2(hrow[c], hrow[c]);
#pragma unroll
        for (int j = 0; j < 8; j++) {
            ulonglong2 w = Wq2[c][j];
            qp[2 * j] = fma2(w.x, hd, qp[2 * j]);
            qp[2 * j + 1] = fma2(w.y, hd, qp[2 * j + 1]);
        }
    }
    u64 qsc = pack2(0.25f, 0.25f);
#pragma unroll
    for (int d = 0; d < 16; d++) qp[d] = mul2(qp[d], qsc);

#pragma unroll
    for (int d = 0; d < 16; d++) tv[d] = 0ULL;
    for (int c = 0; c < 32; c++) {
        u64 hd = pack2(hrow[c], hrow[c]);
#pragma unroll
        for (int j = 0; j < 8; j++) {
            ulonglong2 w = Wk2[c][j];
            tv[2 * j] = fma2(w.x, hd, tv[2 * j]);
            tv[2 * j + 1] = fma2(w.y, hd, tv[2 * j + 1]);
        }
    }
#pragma unroll
    for (int j = 0; j < 8; j++) Kp[t][j] = make_ulonglong2(tv[2 * j], tv[2 * j + 1]);

#pragma unroll
    for (int d = 0; d < 16; d++) tv[d] = 0ULL;
    for (int c = 0; c < 32; c++) {
        u64 hd = pack2(hrow[c], hrow[c]);
#pragma unroll
        for (int j = 0; j < 8; j++) {
            ulonglong2 w = Wv2[c][j];
            tv[2 * j] = fma2(w.x, hd, tv[2 * j]);
            tv[2 * j + 1] = fma2(w.y, hd, tv[2 * j + 1]);
        }
    }
#pragma unroll
    for (int j = 0; j < 8; j++) Vp[t][j] = make_ulonglong2(tv[2 * j], tv[2 * j + 1]);
    __syncthreads();
    for (int idx = t; idx < 512; idx += 128) {
        int c = idx >> 4, d = idx & 15;
        Wq2u[c * 16 + d] = pack2(wo[c * 32 + d], wo[c * 32 + d + 16]);
    }

    float m0 = -3e38f, l0 = 0.f, m1 = -3e38f, l1 = 0.f;
    u64 acc[16];
#pragma unroll
    for (int d = 0; d < 16; d++) acc[d] = 0ULL;
    for (int kp = 0; kp < 128; kp++) {
        u64 s = 0ULL;
#pragma unroll
        for (int j = 0; j < 8; j++) {
            ulonglong2 k2 = Kp[kp][j];
            s = fma2(qp[2 * j], k2.x, s);
            s = fma2(qp[2 * j + 1], k2.y, s);
        }
        float s0, s1; unpack2(s, s0, s1);
        float nm0 = fmaxf(m0, s0), nm1 = fmaxf(m1, s1);
        float cf0 = __expf(m0 - nm0), cf1 = __expf(m1 - nm1);
        float p0 = __expf(s0 - nm0), p1 = __expf(s1 - nm1);
        l0 = l0 * cf0 + p0; l1 = l1 * cf1 + p1;
        m0 = nm0; m1 = nm1;
        u64 cfp = pack2(cf0, cf1), pp = pack2(p0, p1);
#pragma unroll
        for (int j = 0; j < 8; j++) {
            ulonglong2 v2 = Vp[kp][j];
            acc[2 * j] = fma2(acc[2 * j], cfp, mul2(pp, v2.x));
            acc[2 * j + 1] = fma2(acc[2 * j + 1], cfp, mul2(pp, v2.y));
        }
    }
    u64 inv = pack2(1.f / l0, 1.f / l1);
    float ov[32];
#pragma unroll
    for (int d = 0; d < 16; d++) {
        u64 a = mul2(acc[d], inv);
        unpack2(a, ov[d], ov[d + 16]);
    }
    __syncthreads();

    u64 rp[16];
#pragma unroll
    for (int d = 0; d < 16; d++)
        rp[d] = pack2(seq[t * 32 + d], seq[t * 32 + d + 16]);
    for (int c = 0; c < 32; c++) {
        u64 od = pack2(ov[c], ov[c]);
#pragma unroll
        for (int j = 0; j < 8; j++) {
            ulonglong2 w = Wq2[c][j];
            rp[2 * j] = fma2(w.x, od, rp[2 * j]);
            rp[2 * j + 1] = fma2(w.y, od, rp[2 * j + 1]);
        }
    }
    float r[32];
#pragma unroll
    for (int d = 0; d < 16; d++) unpack2(rp[d], r[d], r[d + 16]);
    float mu = 0.f;
#pragma unroll
    for (int o = 0; o < 32; o++) mu += r[o];
    mu *= (1.f / 32.f);
    float var = 0.f;
#pragma unroll
    for (int o = 0; o < 32; o++) { float d = r[o] - mu; var += d * d; }
    var *= (1.f / 32.f);
    float rs = rsqrtf(var + 1e-5f);
#pragma unroll
    for (int o = 0; o < 32; o++) r[o] = (r[o] - mu) * rs * gs[o] + bs2[o];

    if (finalOut == nullptr) {
#pragma unroll
        for (int o4 = 0; o4 < 8; o4++)
            *(float4*)&seq[t * 32 + o4 * 4] =
                make_float4(r[o4 * 4], r[o4 * 4 + 1], r[o4 * 4 + 2], r[o4 * 4 + 3]);
    } else {
        int n = blockIdx.x >> 2, b = blockIdx.x & 3;
        float* dst = finalOut + ((b * T_ + t) * N_ + n) * D_;
#pragma unroll
        for (int o4 = 0; o4 < 8; o4++)
            *(float4*)&dst[o4 * 4] =
                make_float4(r[o4 * 4], r[o4 * 4 + 1], r[o4 * 4 + 2], r[o4 * 4 + 3]);
    }
}

// ---------------- launcher ---------------------------------------------------
extern "C" void kernel_launch(void* const* d_in, const int* in_sizes, int n_in,
                              void* d_out, int out_size) {
    (void)in_sizes; (void)n_in; (void)out_size;
    const float* x   = (const float*)d_in[0];
    const float* E   = (const float*)d_in[2];
    const float* adj = (const float*)d_in[3];
    const float* gw  = (const float*)d_in[4];
    const float* gb  = (const float*)d_in[5];
    const float* tw1 = (const float*)d_in[6];
    const float* tb1 = (const float*)d_in[7];
    const float* tw2 = (const float*)d_in[8];
    const float* tb2 = (const float*)d_in[9];
    const float* awq = (const float*)d_in[10];
    const float* awk = (const float*)d_in[11];
    const float* awv = (const float*)d_in[12];
    const float* awo = (const float*)d_in[13];
    const float* ag  = (const float*)d_in[14];
    const float* ab  = (const float*)d_in[15];
    float* out = (float*)d_out;

    cudaFuncSetAttribute(k_tcn, cudaFuncAttributeMaxDynamicSharedMemorySize,
                         TCN_SMEM);
    cudaFuncSetAttribute(k_aggM, cudaFuncAttributeMaxDynamicSharedMemorySize,
                         AGG_SMEM);

    k_transpose<<<dim3(N_, 8), 256>>>(x);
    k_s2<<<dim3(16, 16), 256>>>(adj);
    k_wn<<<dim3(N_, 3), 256>>>(E, gw, gb);
    k_prep<<<1024, 256>>>(adj);

    // GCN layer 0: buf0 -> buf1; layer 1: buf1 -> buf0; layer 2: buf0 -> buf1
    k_aggM<<<dim3(128, 8), 256, AGG_SMEM>>>();
    k_combine<<<dim3(N_, 8), 128>>>(0, 0, 1);
    k_aggM<<<dim3(128, 8), 256, AGG_SMEM>>>();
    k_combine<<<dim3(N_, 8), 128>>>(1, 1, 1);
    k_aggM<<<dim3(128, 8), 256, AGG_SMEM>>>();
    k_combine<<<dim3(N_, 8), 128>>>(0, 2, 0);

    // TCN in-place on buf1, 2 sequences per block
    k_tcn<<<N_ * B_ / 2, 128, TCN_SMEM>>>(tw1, tb1, tw2, tb2, 1);

    // attention layers (in-place on buf1; last writes transposed final output)
    k_attn<<<N_ * B_, 128>>>(awq, awk, awv, awo, ag, ab, 1, nullptr);
    k_attn<<<N_ * B_, 128>>>(awq + 1024, awk + 1024, awv + 1024, awo + 1024,
                             ag + 32, ab + 32, 1, out);
}

// round 10
// speedup vs baseline: 1.9172x; 1.0451x over previous
#include <cuda_runtime.h>
#include <cuda_bf16.h>

#define B_ 4
#define T_ 128
#define N_ 512
#define D_ 32
#define JN_ 16384       // (B*T)*D
#define EMB_ 10

typedef unsigned long long u64;
typedef unsigned int u32;

// ---------------- f32x2 packed helpers (sm_103a FFMA2) -----------------------
__device__ __forceinline__ u64 pack2(float lo, float hi) {
    u64 r; asm("mov.b64 %0, {%1, %2};" : "=l"(r) : "f"(lo), "f"(hi)); return r;
}
__device__ __forceinline__ void unpack2(u64 v, float& lo, float& hi) {
    asm("mov.b64 {%0, %1}, %2;" : "=f"(lo), "=f"(hi) : "l"(v));
}
__device__ __forceinline__ u64 fma2(u64 a, u64 b, u64 c) {
    u64 d; asm("fma.rn.f32x2 %0, %1, %2, %3;" : "=l"(d) : "l"(a), "l"(b), "l"(c)); return d;
}
__device__ __forceinline__ u64 mul2(u64 a, u64 b) {
    u64 d; asm("mul.rn.f32x2 %0, %1, %2;" : "=l"(d) : "l"(a), "l"(b)); return d;
}
__device__ __forceinline__ u64 add2(u64 a, u64 b) {
    u64 d; asm("add.rn.f32x2 %0, %1, %2;" : "=l"(d) : "l"(a), "l"(b)); return d;
}
__device__ __forceinline__ u64 relu2(u64 v) {
    float a, b; unpack2(v, a, b);
    return pack2(fmaxf(a, 0.f), fmaxf(b, 0.f));
}
__device__ __forceinline__ u32 smem_u32(const void* p) {
    u32 a;
    asm("{ .reg .u64 t; cvta.to.shared.u64 t, %1; cvt.u32.u64 %0, t; }"
        : "=r"(a) : "l"(p));
    return a;
}
// ---------------- mma.sync helpers (sm_80+ path, HMMA on sm_103) ------------
__device__ __forceinline__ void ldmx4(u32& r0, u32& r1, u32& r2, u32& r3, u32 a) {
    asm volatile("ldmatrix.sync.aligned.m8n8.x4.shared.b16 {%0,%1,%2,%3}, [%4];"
                 : "=r"(r0), "=r"(r1), "=r"(r2), "=r"(r3) : "r"(a));
}
__device__ __forceinline__ void ldmx4t(u32& r0, u32& r1, u32& r2, u32& r3, u32 a) {
    asm volatile("ldmatrix.sync.aligned.m8n8.x4.trans.shared.b16 {%0,%1,%2,%3}, [%4];"
                 : "=r"(r0), "=r"(r1), "=r"(r2), "=r"(r3) : "r"(a));
}
__device__ __forceinline__ void mma16816(float* c, const u32* a, const u32* b) {
    asm volatile(
        "mma.sync.aligned.m16n8k16.row.col.f32.bf16.bf16.f32 "
        "{%0,%1,%2,%3}, {%4,%5,%6,%7}, {%8,%9}, {%0,%1,%2,%3};"
        : "+f"(c[0]), "+f"(c[1]), "+f"(c[2]), "+f"(c[3])
        : "r"(a[0]), "r"(a[1]), "r"(a[2]), "r"(a[3]), "r"(b[0]), "r"(b[1]));
}
__device__ __forceinline__ void cpa16(u32 dst, const void* src) {
    asm volatile("cp.async.cg.shared.global [%0], [%1], 16;"
                 :: "r"(dst), "l"(src));
}

// ---------------- scratch (device globals; no allocations allowed) ----------
__device__ float g_buf0[N_ * JN_];       // layout (n, bt, c), bt = b*T+t
__device__ float g_buf1[N_ * JN_];
__device__ float g_xg[2 * N_ * JN_];     // aggregated supports k=1,2
__device__ float g_W[3 * N_ * 3 * D_ * D_];   // per-layer per-node (k,c,o)
__device__ float g_bias[3 * N_ * D_];
// bf16 2-term splits
__device__ __nv_bfloat16 g_A0[1024 * 512], g_A1[1024 * 512];
__device__ __nv_bfloat16 g_B0[N_ * JN_], g_B1[N_ * JN_];

// ---------------- transpose x (bt,n,c) -> (n,bt,c), fused bf16 split --------
__global__ void k_transpose(const float* __restrict__ x) {
    int n = blockIdx.x, bt0 = blockIdx.y * 64, tid = threadIdx.x;
#pragma unroll
    for (int j = 0; j < 8; j++) {
        int idx = j * 256 + tid;
        int r = idx >> 5, c = idx & 31;
        float v = x[(bt0 + r) * (N_ * D_) + n * D_ + c];
        int di = n * JN_ + (bt0 + r) * D_ + c;
        g_buf0[di] = v;
        __nv_bfloat16 h = __float2bfloat16_rn(v);
        g_B0[di] = h;
        g_B1[di] = __float2bfloat16_rn(v - __bfloat162float(h));
    }
}

// ---------------- S2 = 2*adj@adj - I, fused bf16 split ----------------------
__global__ void k_s2(const float* __restrict__ A) {
    __shared__ float As[32][33], Bs[32][33];
    int by = blockIdx.y, bx = blockIdx.x, tid = threadIdx.x;
    int ty = tid >> 5, tx = tid & 31;
    float acc[4] = {0.f, 0.f, 0.f, 0.f};
    for (int m0 = 0; m0 < N_; m0 += 32) {
#pragma unroll
        for (int i = 0; i < 4; i++) {
            int r = ty + i * 8;
            As[r][tx] = A[(by * 32 + r) * N_ + m0 + tx];
            Bs[r][tx] = A[(m0 + r) * N_ + bx * 32 + tx];
        }
        __syncthreads();
#pragma unroll
        for (int m = 0; m < 32; m++) {
            float b = Bs[m][tx];
#pragma unroll
            for (int i = 0; i < 4; i++) acc[i] += As[ty + i * 8][m] * b;
        }
        __syncthreads();
    }
#pragma unroll
    for (int i = 0; i < 4; i++) {
        int r = by * 32 + ty + i * 8, c = bx * 32 + tx;
        float v = 2.f * acc[i] - (r == c ? 1.f : 0.f);
        __nv_bfloat16 h = __float2bfloat16_rn(v);
        g_A0[(512 + r) * 512 + c] = h;
        g_A1[(512 + r) * 512 + c] = __float2bfloat16_rn(v - __bfloat162float(h));
    }
}

// ---------------- per-node GCN weights --------------------------------------
__global__ void k_wn(const float* __restrict__ E, const float* __restrict__ gw,
                     const float* __restrict__ gb) {
    int n = blockIdx.x, L = blockIdx.y, tid = threadIdx.x;
    float Er[EMB_];
#pragma unroll
    for (int e = 0; e < EMB_; e++) Er[e] = E[n * EMB_ + e];
    const float* g0 = gw + L * (EMB_ * 3072);
    float* wout = g_W + (L * N_ + n) * 3072;
    for (int idx = tid; idx < 3072; idx += 256) {
        float a = 0.f;
#pragma unroll
        for (int e = 0; e < EMB_; e++) a += Er[e] * g0[e * 3072 + idx];
        wout[idx] = a;
    }
    if (tid < 32) {
        const float* b0 = gb + L * (EMB_ * 32);
        float a = 0.f;
#pragma unroll
        for (int e = 0; e < EMB_; e++) a += Er[e] * b0[e * 32 + tid];
        g_bias[(L * N_ + n) * 32 + tid] = a;
    }
}

// ---------------- bf16 2-term split of adj rows (S2 handled by k_s2) --------
__global__ void k_prep(const float* __restrict__ adj) {
    int r = blockIdx.x, tid = threadIdx.x;
    const float* src = &adj[r * 512];
    for (int c = tid; c < 512; c += 256) {
        float v = src[c];
        __nv_bfloat16 h = __float2bfloat16_rn(v);
        g_A0[r * 512 + c] = h;
        g_A1[r * 512 + c] = __float2bfloat16_rn(v - __bfloat162float(h));
    }
}

// ---------------- tensor-core aggregation GEMM via mma.sync -----------------
#define AGG_STAGE 37888
#define AGG_SMEM (2 * AGG_STAGE)    // 75776
__global__ void __launch_bounds__(256) k_aggM() {
    extern __shared__ char smdyn[];
    u32 sbase = smem_u32(smdyn);
    int tid = threadIdx.x, lane = tid & 31, wid = tid >> 5;
    int j0 = blockIdx.x * 128, i0 = blockIdx.y * 128;
    int wm = wid >> 2, wj = wid & 3;
    int lr = lane & 15, lh = lane >> 4;
    float acc[4][4][4];
#pragma unroll
    for (int mt = 0; mt < 4; mt++)
#pragma unroll
        for (int nt = 0; nt < 4; nt++)
#pragma unroll
            for (int q = 0; q < 4; q++) acc[mt][nt][q] = 0.f;

    auto loadStage = [&](int ch, int st) {
        u32 sb = sbase + st * AGG_STAGE;
        int k0 = ch * 32;
#pragma unroll
        for (int it = 0; it < 2; it++) {
            int idx = it * 256 + tid;
            int row = idx >> 2, c16 = idx & 3;
            cpa16(sb + row * 80 + c16 * 16,
                  &g_A0[(i0 + row) * 512 + k0 + c16 * 8]);
            cpa16(sb + 10240 + row * 80 + c16 * 16,
                  &g_A1[(i0 + row) * 512 + k0 + c16 * 8]);
        }
#pragma unroll
        for (int it = 0; it < 2; it++) {
            int idx = it * 256 + tid;
            int k = idx >> 4, c = idx & 15;
            cpa16(sb + 20480 + k * 272 + c * 16,
                  &g_B0[(size_t)(k0 + k) * JN_ + j0 + c * 8]);
            cpa16(sb + 29184 + k * 272 + c * 16,
                  &g_B1[(size_t)(k0 + k) * JN_ + j0 + c * 8]);
        }
        asm volatile("cp.async.commit_group;" ::: "memory");
    };

    loadStage(0, 0);
    for (int ch = 0; ch < 16; ch++) {
        if (ch + 1 < 16) {
            loadStage(ch + 1, (ch + 1) & 1);
            asm volatile("cp.async.wait_group 1;" ::: "memory");
        } else {
            asm volatile("cp.async.wait_group 0;" ::: "memory");
        }
        __syncthreads();
        u32 sb = sbase + (ch & 1) * AGG_STAGE;
        u32 aH = sb, aM = sb + 10240, bH = sb + 20480, bM = sb + 29184;
#pragma unroll
        for (int s2 = 0; s2 < 32; s2 += 16) {
            u32 bh[4][2], bm[4][2];
#pragma unroll
            for (int half = 0; half < 2; half++) {
                u32 boff = (u32)((s2 + lr) * 272 +
                                 (wj * 32 + half * 16 + lh * 8) * 2);
                u32 r0, r1, r2, r3;
                ldmx4t(r0, r1, r2, r3, bH + boff);
                bh[half * 2][0] = r0; bh[half * 2][1] = r1;
                bh[half * 2 + 1][0] = r2; bh[half * 2 + 1][1] = r3;
                ldmx4t(r0, r1, r2, r3, bM + boff);
                bm[half * 2][0] = r0; bm[half * 2][1] = r1;
                bm[half * 2 + 1][0] = r2; bm[half * 2 + 1][1] = r3;
            }
#pragma unroll
            for (int mt = 0; mt < 4; mt++) {
                u32 aoff = (u32)((wm * 64 + mt * 16 + lr) * 80 +
                                 (s2 + lh * 8) * 2);
                u32 ah[4], am[4];
                ldmx4(ah[0], ah[1], ah[2], ah[3], aH + aoff);
                ldmx4(am[0], am[1], am[2], am[3], aM + aoff);
#pragma unroll
                for (int nt = 0; nt < 4; nt++) {
                    mma16816(acc[mt][nt], ah, bh[nt]);
                    mma16816(acc[mt][nt], ah, bm[nt]);
                    mma16816(acc[mt][nt], am, bh[nt]);
                }
            }
        }
        __syncthreads();
    }
    int rbase = i0 + wm * 64 + (lane >> 2);
    int cbase = j0 + wj * 32 + 2 * (lane & 3);
#pragma unroll
    for (int mt = 0; mt < 4; mt++)
#pragma unroll
        for (int nt = 0; nt < 4; nt++) {
            size_t base = (size_t)(rbase + mt * 16) * JN_ + cbase + nt * 8;
            *(float2*)&g_xg[base] = make_float2(acc[mt][nt][0], acc[mt][nt][1]);
            *(float2*)&g_xg[base + 8 * JN_] =
                make_float2(acc[mt][nt][2], acc[mt][nt][3]);
        }
}

// ---------------- combine: out = [H|xg1|xg2] @ W[n] + b[n], fused split -----
__global__ void k_combine(int inSel, int L, int doSplit) {
    __shared__ float Xin[96][68];
    __shared__ float Ws[3072];
    __shared__ float bs[32];
    const float* Hin = inSel ? g_buf1 : g_buf0;
    float* Hout = inSel ? g_buf0 : g_buf1;
    int n = blockIdx.x, bt0 = blockIdx.y * 64, tid = threadIdx.x;
    const float* Wl = g_W + (L * N_ + n) * 3072;
    for (int q = tid; q < 3072; q += 128) Ws[q] = Wl[q];
    if (tid < 32) bs[tid] = g_bias[(L * N_ + n) * 32 + tid];
    const float* s0 = Hin + n * JN_ + bt0 * D_;
    const float* s1 = g_xg + n * JN_ + bt0 * D_;
    const float* s2 = g_xg + (N_ + n) * JN_ + bt0 * D_;
#pragma unroll
    for (int q = tid; q < 2048; q += 128) {
        int r = q >> 5, c = q & 31;
        Xin[c][r] = s0[q];
        Xin[32 + c][r] = s1[q];
        Xin[64 + c][r] = s2[q];
    }
    __syncthreads();
    int to = tid & 7, tb = tid >> 3;
    float acc[4][4];
#pragma unroll
    for (int i = 0; i < 4; i++)
#pragma unroll
        for (int j = 0; j < 4; j++) acc[i][j] = 0.f;
    for (int kc = 0; kc < 96; kc++) {
        float4 xv = *(const float4*)&Xin[kc][tb * 4];
        float4 wv = *(const float4*)&Ws[kc * 32 + to * 4];
        acc[0][0] += xv.x * wv.x; acc[0][1] += xv.x * wv.y;
        acc[0][2] += xv.x * wv.z; acc[0][3] += xv.x * wv.w;
        acc[1][0] += xv.y * wv.x; acc[1][1] += xv.y * wv.y;
        acc[1][2] += xv.y * wv.z; acc[1][3] += xv.y * wv.w;
        acc[2][0] += xv.z * wv.x; acc[2][1] += xv.z * wv.y;
        acc[2][2] += xv.z * wv.z; acc[2][3] += xv.z * wv.w;
        acc[3][0] += xv.w * wv.x; acc[3][1] += xv.w * wv.y;
        acc[3][2] += xv.w * wv.z; acc[3][3] += xv.w * wv.w;
    }
    float4 bv = *(const float4*)&bs[to * 4];
#pragma unroll
    for (int i = 0; i < 4; i++) {
        int bt = bt0 + tb * 4 + i;
        float o0 = acc[i][0] + bv.x, o1 = acc[i][1] + bv.y;
        float o2 = acc[i][2] + bv.z, o3 = acc[i][3] + bv.w;
        int di = n * JN_ + bt * D_ + to * 4;
        *(float4*)&Hout[di] = make_float4(o0, o1, o2, o3);
        if (doSplit) {
            float vv[4] = {o0, o1, o2, o3};
            unsigned short hs[4], ms[4];
#pragma unroll
            for (int q = 0; q < 4; q++) {
                __nv_bfloat16 h = __float2bfloat16_rn(vv[q]);
                hs[q] = __bfloat16_as_ushort(h);
                ms[q] = __bfloat16_as_ushort(
                    __float2bfloat16_rn(vv[q] - __bfloat162float(h)));
            }
            *(uint2*)&g_B0[di] = make_uint2((u32)hs[0] | ((u32)hs[1] << 16),
                                            (u32)hs[2] | ((u32)hs[3] << 16));
            *(uint2*)&g_B1[di] = make_uint2((u32)ms[0] | ((u32)ms[1] << 16),
                                            (u32)ms[2] | ((u32)ms[3] << 16));
        }
    }
}

// ---------------- fused TCN: f32x2-packed, 2 sequences per block ------------
#define TCN_SMEM 90880
__global__ void __launch_bounds__(128)
k_tcn(const float* __restrict__ w1, const float* __restrict__ b1,
      const float* __restrict__ w2, const float* __restrict__ b2, int sel) {
    extern __shared__ char dsm[];
    ulonglong2* e01 = (ulonglong2*)dsm;
    u64* wd2 = (u64*)(dsm + 16384);
    u64* bb  = (u64*)(dsm + 16384 + 8192);
    u64 (*y0)[129] = (u64(*)[129])(dsm + 24832);
    u64 (*y1)[129] = (u64(*)[129])(dsm + 24832 + 33024);

    float* base = sel ? g_buf1 : g_buf0;
    float* seqA = base + (2 * blockIdx.x) * 4096;
    float* seqB = seqA + 4096;
    int t = threadIdx.x;

#pragma unroll
    for (int j = 0; j < 32; j++) {
        int idx = j * 128 + t;
        int c = idx & 31, tt = idx >> 5;
        y0[c][tt] = pack2(seqA[idx], seqB[idx]);
    }
    for (int blk = 0; blk < 3; blk++) {
        int dil = 1 << blk;
        __syncthreads();
        const float* ws = w1 + blk * 3072;
        for (int q = t; q < 1024; q += 128) {
            float a = ws[q * 3], b = ws[q * 3 + 1], c = ws[q * 3 + 2];
            e01[q] = make_ulonglong2(pack2(a, a), pack2(b, b));
            wd2[q] = pack2(c, c);
        }
        if (t < 32) { float v = b1[blk * 32 + t]; bb[t] = pack2(v, v); }
        __syncthreads();
        u64 acc[32];
#pragma unroll
        for (int o = 0; o < 32; o++) acc[o] = bb[o];
        for (int c = 0; c < 32; c++) {
            u64 i0 = (t >= 2 * dil) ? y0[c][t - 2 * dil] : 0ULL;
            u64 i1 = (t >= dil) ? y0[c][t - dil] : 0ULL;
            u64 i2 = y0[c][t];
#pragma unroll
            for (int o = 0; o < 32; o++) {
                ulonglong2 w01 = e01[o * 32 + c];
                acc[o] = fma2(w01.x, i0, acc[o]);
                acc[o] = fma2(w01.y, i1, acc[o]);
                acc[o] = fma2(wd2[o * 32 + c], i2, acc[o]);
            }
        }
#pragma unroll
        for (int o = 0; o < 32; o++) y1[o][t] = relu2(acc[o]);
        __syncthreads();
        const float* ws2 = w2 + blk * 3072;
        for (int q = t; q < 1024; q += 128) {
            float a = ws2[q * 3], b = ws2[q * 3 + 1], c = ws2[q * 3 + 2];
            e01[q] = make_ulonglong2(pack2(a, a), pack2(b, b));
            wd2[q] = pack2(c, c);
        }
        if (t < 32) { float v = b2[blk * 32 + t]; bb[t] = pack2(v, v); }
        __syncthreads();
#pragma unroll
        for (int o = 0; o < 32; o++) acc[o] = bb[o];
        for (int c = 0; c < 32; c++) {
            u64 i0 = (t >= 2 * dil) ? y1[c][t - 2 * dil] : 0ULL;
            u64 i1 = (t >= dil) ? y1[c][t - dil] : 0ULL;
            u64 i2 = y1[c][t];
#pragma unroll
            for (int o = 0; o < 32; o++) {
                ulonglong2 w01 = e01[o * 32 + c];
                acc[o] = fma2(w01.x, i0, acc[o]);
                acc[o] = fma2(w01.y, i1, acc[o]);
                acc[o] = fma2(wd2[o * 32 + c], i2, acc[o]);
            }
        }
#pragma unroll
        for (int o = 0; o < 32; o++)
            y0[o][t] = relu2(add2(relu2(acc[o]), y0[o][t]));
    }
    __syncthreads();
#pragma unroll
    for (int j = 0; j < 32; j++) {
        int idx = j * 128 + t;
        int c = idx & 31, tt = idx >> 5;
        float lo, hi; unpack2(y0[c][tt], lo, hi);
        seqA[idx] = lo; seqB[idx] = hi;
    }
}

// ---------------- merged 2-layer temporal attention + layernorm -------------
// layer-1 output stays in registers as layer-2 input; tiled online softmax.
__global__ void __launch_bounds__(128)
k_attn2(const float* __restrict__ wq, const float* __restrict__ wk,
        const float* __restrict__ wv, const float* __restrict__ wo,
        const float* __restrict__ gga, const float* __restrict__ bba,
        int sel, float* __restrict__ finalOut) {
    __shared__ ulonglong2 Kp[128][8];
    __shared__ ulonglong2 Vp[128][8];
    __shared__ ulonglong2 Wq2[32][8];   // reused for Wo
    __shared__ ulonglong2 Wk2[32][8];
    __shared__ ulonglong2 Wv2[32][8];
    __shared__ float gs[2][32], bs2[2][32];
    const float* seq = (sel ? g_buf1 : g_buf0) + blockIdx.x * 4096;
    int t = threadIdx.x;
    u64* Wq2u = (u64*)Wq2; u64* Wk2u = (u64*)Wk2; u64* Wv2u = (u64*)Wv2;

    if (t < 64) {
        int L = t >> 5, o = t & 31;
        gs[L][o] = gga[L * 32 + o];
        bs2[L][o] = bba[L * 32 + o];
    }
    float hrow[32];
#pragma unroll
    for (int o4 = 0; o4 < 8; o4++)
        *(float4*)&hrow[o4 * 4] = *(const float4*)&seq[t * 32 + o4 * 4];

    for (int L = 0; L < 2; L++) {
        __syncthreads();   // prior-layer Wo reads done (no-op cost at L=0)
        const float* wqL = wq + L * 1024;
        const float* wkL = wk + L * 1024;
        const float* wvL = wv + L * 1024;
        for (int idx = t; idx < 512; idx += 128) {
            int c = idx >> 4, d = idx & 15;
            Wq2u[c * 16 + d] = pack2(wqL[c * 32 + d], wqL[c * 32 + d + 16]);
            Wk2u[c * 16 + d] = pack2(wkL[c * 32 + d], wkL[c * 32 + d + 16]);
            Wv2u[c * 16 + d] = pack2(wvL[c * 32 + d], wvL[c * 32 + d + 16]);
        }
        __syncthreads();

        u64 qp[16], tv[16];
#pragma unroll
        for (int d = 0; d < 16; d++) qp[d] = 0ULL;
        for (int c = 0; c < 32; c++) {
            u64 hd = pack2(hrow[c], hrow[c]);
#pragma unroll
            for (int j = 0; j < 8; j++) {
                ulonglong2 w = Wq2[c][j];
                qp[2 * j] = fma2(w.x, hd, qp[2 * j]);
                qp[2 * j + 1] = fma2(w.y, hd, qp[2 * j + 1]);
            }
        }
        u64 qsc = pack2(0.25f, 0.25f);   // 1/sqrt(16)
#pragma unroll
        for (int d = 0; d < 16; d++) qp[d] = mul2(qp[d], qsc);

#pragma unroll
        for (int d = 0; d < 16; d++) tv[d] = 0ULL;
        for (int c = 0; c < 32; c++) {
            u64 hd = pack2(hrow[c], hrow[c]);
#pragma unroll
            for (int j = 0; j < 8; j++) {
                ulonglong2 w = Wk2[c][j];
                tv[2 * j] = fma2(w.x, hd, tv[2 * j]);
                tv[2 * j + 1] = fma2(w.y, hd, tv[2 * j + 1]);
            }
        }
#pragma unroll
        for (int j = 0; j < 8; j++)
            Kp[t][j] = make_ulonglong2(tv[2 * j], tv[2 * j + 1]);

#pragma unroll
        for (int d = 0; d < 16; d++) tv[d] = 0ULL;
        for (int c = 0; c < 32; c++) {
            u64 hd = pack2(hrow[c], hrow[c]);
#pragma unroll
            for (int j = 0; j < 8; j++) {
                ulonglong2 w = Wv2[c][j];
                tv[2 * j] = fma2(w.x, hd, tv[2 * j]);
                tv[2 * j + 1] = fma2(w.y, hd, tv[2 * j + 1]);
            }
        }
#pragma unroll
        for (int j = 0; j < 8; j++)
            Vp[t][j] = make_ulonglong2(tv[2 * j], tv[2 * j + 1]);
        __syncthreads();              // Kp/Vp ready; Wq dead
        const float* woL = wo + L * 1024;
        for (int idx = t; idx < 512; idx += 128) {
            int c = idx >> 4, d = idx & 15;
            Wq2u[c * 16 + d] = pack2(woL[c * 32 + d], woL[c * 32 + d + 16]);
        }

        // ---- tiled online softmax (8 keys per tile) ----
        float m0 = -3e38f, l0 = 0.f, m1 = -3e38f, l1 = 0.f;
        u64 acc[16];
#pragma unroll
        for (int d = 0; d < 16; d++) acc[d] = 0ULL;
        for (int tile = 0; tile < 16; tile++) {
            float sv0[8], sv1[8];
            float ts0 = -3e38f, ts1 = -3e38f;
#pragma unroll
            for (int q = 0; q < 8; q++) {
                int kp = tile * 8 + q;
                u64 s = 0ULL;
#pragma unroll
                for (int j = 0; j < 8; j++) {
                    ulonglong2 k2 = Kp[kp][j];
                    s = fma2(qp[2 * j], k2.x, s);
                    s = fma2(qp[2 * j + 1], k2.y, s);
                }
                unpack2(s, sv0[q], sv1[q]);
                ts0 = fmaxf(ts0, sv0[q]);
                ts1 = fmaxf(ts1, sv1[q]);
            }
            float nm0 = fmaxf(m0, ts0), nm1 = fmaxf(m1, ts1);
            float cf0 = __expf(m0 - nm0), cf1 = __expf(m1 - nm1);
            l0 *= cf0; l1 *= cf1;
            m0 = nm0; m1 = nm1;
            u64 cfp = pack2(cf0, cf1);
#pragma unroll
            for (int d = 0; d < 16; d++) acc[d] = mul2(acc[d], cfp);
#pragma unroll
            for (int q = 0; q < 8; q++) {
                int kp = tile * 8 + q;
                float p0 = __expf(sv0[q] - m0), p1 = __expf(sv1[q] - m1);
                l0 += p0; l1 += p1;
                u64 pp = pack2(p0, p1);
#pragma unroll
                for (int j = 0; j < 8; j++) {
                    ulonglong2 v2 = Vp[kp][j];
                    acc[2 * j] = fma2(pp, v2.x, acc[2 * j]);
                    acc[2 * j + 1] = fma2(pp, v2.y, acc[2 * j + 1]);
                }
            }
        }
        u64 inv = pack2(1.f / l0, 1.f / l1);
        float ov[32];
#pragma unroll
        for (int d = 0; d < 16; d++) {
            u64 a = mul2(acc[d], inv);
            unpack2(a, ov[d], ov[d + 16]);
        }
        __syncthreads();              // Wo overlay fully visible

        u64 rp[16];
#pragma unroll
        for (int d = 0; d < 16; d++)
            rp[d] = pack2(hrow[d], hrow[d + 16]);   // residual from regs
        for (int c = 0; c < 32; c++) {
            u64 od = pack2(ov[c], ov[c]);
#pragma unroll
            for (int j = 0; j < 8; j++) {
                ulonglong2 w = Wq2[c][j];    // Wo
                rp[2 * j] = fma2(w.x, od, rp[2 * j]);
                rp[2 * j + 1] = fma2(w.y, od, rp[2 * j + 1]);
            }
        }
        float r[32];
#pragma unroll
        for (int d = 0; d < 16; d++) unpack2(rp[d], r[d], r[d + 16]);
        float mu = 0.f;
#pragma unroll
        for (int o = 0; o < 32; o++) mu += r[o];
        mu *= (1.f / 32.f);
        float var = 0.f;
#pragma unroll
        for (int o = 0; o < 32; o++) { float d = r[o] - mu; var += d * d; }
        var *= (1.f / 32.f);
        float rs = rsqrtf(var + 1e-5f);
#pragma unroll
        for (int o = 0; o < 32; o++)
            hrow[o] = (r[o] - mu) * rs * gs[L][o] + bs2[L][o];
    }

    int n = blockIdx.x >> 2, b = blockIdx.x & 3;   // seq chunk = n*B + b
    float* dst = finalOut + ((b * T_ + t) * N_ + n) * D_;
#pragma unroll
    for (int o4 = 0; o4 < 8; o4++)
        *(float4*)&dst[o4 * 4] =
            make_float4(hrow[o4 * 4], hrow[o4 * 4 + 1],
                        hrow[o4 * 4 + 2], hrow[o4 * 4 + 3]);
}

// ---------------- launcher ---------------------------------------------------
extern "C" void kernel_launch(void* const* d_in, const int* in_sizes, int n_in,
                              void* d_out, int out_size) {
    (void)in_sizes; (void)n_in; (void)out_size;
    const float* x   = (const float*)d_in[0];
    const float* E   = (const float*)d_in[2];
    const float* adj = (const float*)d_in[3];
    const float* gw  = (const float*)d_in[4];
    const float* gb  = (const float*)d_in[5];
    const float* tw1 = (const float*)d_in[6];
    const float* tb1 = (const float*)d_in[7];
    const float* tw2 = (const float*)d_in[8];
    const float* tb2 = (const float*)d_in[9];
    const float* awq = (const float*)d_in[10];
    const float* awk = (const float*)d_in[11];
    const float* awv = (const float*)d_in[12];
    const float* awo = (const float*)d_in[13];
    const float* ag  = (const float*)d_in[14];
    const float* ab  = (const float*)d_in[15];
    float* out = (float*)d_out;

    cudaFuncSetAttribute(k_tcn, cudaFuncAttributeMaxDynamicSharedMemorySize,
                         TCN_SMEM);
    cudaFuncSetAttribute(k_aggM, cudaFuncAttributeMaxDynamicSharedMemorySize,
                         AGG_SMEM);

    k_transpose<<<dim3(N_, 8), 256>>>(x);
    k_s2<<<dim3(16, 16), 256>>>(adj);
    k_wn<<<dim3(N_, 3), 256>>>(E, gw, gb);
    k_prep<<<512, 256>>>(adj);

    // GCN layer 0: buf0 -> buf1; layer 1: buf1 -> buf0; layer 2: buf0 -> buf1
    k_aggM<<<dim3(128, 8), 256, AGG_SMEM>>>();
    k_combine<<<dim3(N_, 8), 128>>>(0, 0, 1);
    k_aggM<<<dim3(128, 8), 256, AGG_SMEM>>>();
    k_combine<<<dim3(N_, 8), 128>>>(1, 1, 1);
    k_aggM<<<dim3(128, 8), 256, AGG_SMEM>>>();
    k_combine<<<dim3(N_, 8), 128>>>(0, 2, 0);

    // TCN in-place on buf1, 2 sequences per block
    k_tcn<<<N_ * B_ / 2, 128, TCN_SMEM>>>(tw1, tb1, tw2, tb2, 1);

    // merged 2-layer attention; writes transposed final output
    k_attn2<<<N_ * B_, 128>>>(awq, awk, awv, awo, ag, ab, 1, out);
}